// round 8
// baseline (speedup 1.0000x reference)
#include <cuda_runtime.h>
#include <cstdint>

#define BB 2
#define SS 2048
#define EE 1024
#define HH 16
#define DHD 64
#define ME (4096 * 1024)
#define NE (1024 * 1024)

// ---------------------------------------------------------------------------
// PTX helpers (base-sm_103 features only)
// ---------------------------------------------------------------------------
__device__ __forceinline__ uint32_t smem_u32(const void* p) {
    uint32_t a;
    asm("{ .reg .u64 t; cvta.to.shared.u64 t, %1; cvt.u32.u64 %0, t; }" : "=r"(a) : "l"(p));
    return a;
}
__device__ __forceinline__ void ldsm4(uint32_t r[4], uint32_t a) {
    asm volatile("ldmatrix.sync.aligned.m8n8.x4.shared.b16 {%0,%1,%2,%3}, [%4];"
                 : "=r"(r[0]), "=r"(r[1]), "=r"(r[2]), "=r"(r[3]) : "r"(a));
}
__device__ __forceinline__ void ldsm4t(uint32_t r[4], uint32_t a) {
    asm volatile("ldmatrix.sync.aligned.m8n8.x4.trans.shared.b16 {%0,%1,%2,%3}, [%4];"
                 : "=r"(r[0]), "=r"(r[1]), "=r"(r[2]), "=r"(r[3]) : "r"(a));
}
__device__ __forceinline__ void mma_bf16(float d[4], const uint32_t a[4], const uint32_t b[2]) {
    asm volatile("mma.sync.aligned.m16n8k16.row.col.f32.bf16.bf16.f32 "
                 "{%0,%1,%2,%3}, {%4,%5,%6,%7}, {%8,%9}, {%0,%1,%2,%3};"
                 : "+f"(d[0]), "+f"(d[1]), "+f"(d[2]), "+f"(d[3])
                 : "r"(a[0]), "r"(a[1]), "r"(a[2]), "r"(a[3]), "r"(b[0]), "r"(b[1]));
}
// split fp32 pair -> bf16x2 hi + bf16x2 lo (x = hi + lo, exact residual)
__device__ __forceinline__ void split2(float2 v, uint32_t& hi, uint32_t& lo) {
    asm("cvt.rn.bf16x2.f32 %0, %1, %2;" : "=r"(hi) : "f"(v.y), "f"(v.x));
    float h0 = __uint_as_float(hi << 16);
    float h1 = __uint_as_float(hi & 0xFFFF0000u);
    asm("cvt.rn.bf16x2.f32 %0, %1, %2;" : "=r"(lo) : "f"(v.y - h1), "f"(v.x - h0));
}
__device__ __forceinline__ void cpa16(uint32_t dst, const void* src) {
    asm volatile("cp.async.cg.shared.global [%0], [%1], 16;" :: "r"(dst), "l"(src));
}
#define CPA_COMMIT() asm volatile("cp.async.commit_group;" ::: "memory")
#define CPA_WAIT1()  asm volatile("cp.async.wait_group 1;" ::: "memory")

// ---------------------------------------------------------------------------
// Global bf16 hi/lo scratch (allocation-free)
// ---------------------------------------------------------------------------
__device__ uint16_t g_ih[3 * ME], g_il[3 * ME];   // split inputs q,k,v
__device__ uint16_t g_wh[4 * NE], g_wl[4 * NE];   // split weights q,k,v,o
__device__ uint16_t g_ph[3 * ME], g_pl[3 * ME];   // projected Q,K,V (hi/lo)
__device__ uint16_t g_oh[ME],     g_ol[ME];       // attention output (hi/lo)

// ---------------------------------------------------------------------------
// Prep: fp32 -> bf16 hi/lo
// ---------------------------------------------------------------------------
__global__ void split_in(const float* s0, const float* s1, const float* s2,
                         uint16_t* dh, uint16_t* dl)
{
    const float* src = (blockIdx.y == 0) ? s0 : (blockIdx.y == 1 ? s1 : s2);
    const float2* sp = (const float2*)src;
    uint32_t* hp = (uint32_t*)(dh + (size_t)blockIdx.y * ME);
    uint32_t* lp = (uint32_t*)(dl + (size_t)blockIdx.y * ME);
    const int n = ME / 2;
    for (int i = blockIdx.x * blockDim.x + threadIdx.x; i < n; i += gridDim.x * blockDim.x) {
        uint32_t h, l;
        split2(sp[i], h, l);
        hp[i] = h; lp[i] = l;
    }
}
__global__ void split_w(const float* s0, const float* s1, const float* s2, const float* s3,
                        uint16_t* dh, uint16_t* dl)
{
    const float* srcs[4] = {s0, s1, s2, s3};
    const float2* sp = (const float2*)srcs[blockIdx.y];
    uint32_t* hp = (uint32_t*)(dh + (size_t)blockIdx.y * NE);
    uint32_t* lp = (uint32_t*)(dl + (size_t)blockIdx.y * NE);
    const int n = NE / 2;
    for (int i = blockIdx.x * blockDim.x + threadIdx.x; i < n; i += gridDim.x * blockDim.x) {
        uint32_t h, l;
        split2(sp[i], h, l);
        hp[i] = h; lp[i] = l;
    }
}

// ---------------------------------------------------------------------------
// Projection GEMM (bf16 hi/lo in): C = (A*W^T + bias) * scale.
// Tile 128x128, BK=32, 32 stages, 2-stage double-buffered cp.async pipeline.
// 256 thr, occ 2. Stage arrays [128][40] bf16 (80B rows, ldsm conflict-free).
// mode 0: fp32 out; mode 1: bf16 hi/lo out.
// ---------------------------------------------------------------------------
#define PJ 40
#define PJB 80
#define PJ_ARR 10240          // 128*80
#define PJ_STG 40960          // 4 arrays
#define PRJ_SMEM 81920        // 2 stages

__device__ __forceinline__ void prj_issue(
    uint32_t smb, int tid, int buf, int kk0, int bm, int bn,
    const uint16_t* Ah, const uint16_t* Al,
    const uint16_t* Wh, const uint16_t* Wl)
{
#pragma unroll
    for (int it = 0; it < 8; it++) {
        int idx = tid + it * 256;          // 0..2047
        int a   = idx >> 9;                // 0 AHI,1 ALO,2 BHI,3 BLO
        int c   = idx & 511;
        int row = c >> 2, cc = c & 3;      // 4 x 16B per 32-col row
        const uint16_t* base =
            (a == 0) ? Ah + (size_t)(bm + row) * EE :
            (a == 1) ? Al + (size_t)(bm + row) * EE :
            (a == 2) ? Wh + (size_t)(bn + row) * EE :
                       Wl + (size_t)(bn + row) * EE;
        cpa16(smb + buf * PJ_STG + a * PJ_ARR + row * PJB + cc * 16,
              base + kk0 + cc * 8);
    }
}

__global__ __launch_bounds__(256, 2)
void gemm_bf(const uint16_t* __restrict__ Ah, const uint16_t* __restrict__ Al,
             const uint16_t* __restrict__ Wh, const uint16_t* __restrict__ Wl,
             const float* __restrict__ bias, float scale, int mode,
             float* __restrict__ Cf, uint16_t* __restrict__ Ch, uint16_t* __restrict__ Cl)
{
    extern __shared__ char sm[];
    const uint32_t smb = smem_u32(sm);
    const int tid = threadIdx.x;
    const int bm = blockIdx.y * 128, bn = blockIdx.x * 128;
    const int w = tid >> 5, lane = tid & 31;
    const int m0 = (w & 1) * 64, n0 = (w >> 1) * 32;
    const int r8 = lane & 7, quad = lane >> 3;
    const int arow = (quad & 1) * 8 + r8, acol = (quad >> 1) * 8;
    const int brow = (quad >> 1) * 8 + r8, bcol = (quad & 1) * 8;

    float acc[4][4][4];
#pragma unroll
    for (int i = 0; i < 4; i++)
#pragma unroll
        for (int j = 0; j < 4; j++)
#pragma unroll
            for (int k = 0; k < 4; k++) acc[i][j][k] = 0.0f;

    prj_issue(smb, tid, 0, 0, bm, bn, Ah, Al, Wh, Wl);
    CPA_COMMIT();
    prj_issue(smb, tid, 1, 32, bm, bn, Ah, Al, Wh, Wl);
    CPA_COMMIT();

    for (int s = 0; s < 32; s++) {
        CPA_WAIT1();
        __syncthreads();
        const uint32_t stg = smb + (s & 1) * PJ_STG;

#pragma unroll
        for (int kf = 0; kf < 2; kf++) {
            uint32_t bh[4][2], bl[4][2], t[4];
#pragma unroll
            for (int np = 0; np < 2; np++) {
                uint32_t boff = (uint32_t)((n0 + np * 16 + brow) * PJ + kf * 16 + bcol) * 2;
                ldsm4(t, stg + 2 * PJ_ARR + boff);
                bh[np * 2][0] = t[0]; bh[np * 2][1] = t[1];
                bh[np * 2 + 1][0] = t[2]; bh[np * 2 + 1][1] = t[3];
                ldsm4(t, stg + 3 * PJ_ARR + boff);
                bl[np * 2][0] = t[0]; bl[np * 2][1] = t[1];
                bl[np * 2 + 1][0] = t[2]; bl[np * 2 + 1][1] = t[3];
            }
#pragma unroll
            for (int mf = 0; mf < 4; mf++) {
                uint32_t ah[4], al[4];
                uint32_t aoff = (uint32_t)((m0 + mf * 16 + arow) * PJ + kf * 16 + acol) * 2;
                ldsm4(ah, stg + aoff);
                ldsm4(al, stg + PJ_ARR + aoff);
#pragma unroll
                for (int nf = 0; nf < 4; nf++) {
                    mma_bf16(acc[mf][nf], ah, bh[nf]);
                    mma_bf16(acc[mf][nf], ah, bl[nf]);
                    mma_bf16(acc[mf][nf], al, bh[nf]);
                }
            }
        }
        __syncthreads();
        if (s + 2 < 32)
            prj_issue(smb, tid, s & 1, (s + 2) * 32, bm, bn, Ah, Al, Wh, Wl);
        CPA_COMMIT();
    }

    const int g2 = lane >> 2, t2 = (lane & 3) * 2;
#pragma unroll
    for (int mf = 0; mf < 4; mf++)
#pragma unroll
        for (int nf = 0; nf < 4; nf++) {
            int row0 = bm + m0 + mf * 16 + g2;
            int col = bn + n0 + nf * 8 + t2;
            float b0 = bias[col], b1 = bias[col + 1];
            float v0 = (acc[mf][nf][0] + b0) * scale, v1 = (acc[mf][nf][1] + b1) * scale;
            float v2 = (acc[mf][nf][2] + b0) * scale, v3 = (acc[mf][nf][3] + b1) * scale;
            if (mode == 0) {
                *(float2*)(Cf + (size_t)row0 * EE + col) = make_float2(v0, v1);
                *(float2*)(Cf + (size_t)(row0 + 8) * EE + col) = make_float2(v2, v3);
            } else {
                uint32_t hi, lo;
                size_t off = (size_t)row0 * EE + col;
                split2(make_float2(v0, v1), hi, lo);
                *(uint32_t*)(Ch + off) = hi;
                *(uint32_t*)(Cl + off) = lo;
                split2(make_float2(v2, v3), hi, lo);
                off += (size_t)8 * EE;
                *(uint32_t*)(Ch + off) = hi;
                *(uint32_t*)(Cl + off) = lo;
            }
        }
}

// ---------------------------------------------------------------------------
// Fused attention (bf16 hi/lo in, hi/lo out). NO softmax. Q pre-scaled by 1/8.
// q-tile 128; K/V streamed in 64-row half-tiles, double-buffered cp.async.
// ---------------------------------------------------------------------------
#define GP 72
#define GPB 144
#define AQH 0
#define AQL 18432
#define AKB(st) (36864 + (st) * 18432)
#define AVB(st) (73728 + (st) * 18432)
#define ASH 110592
#define ASL 129024
#define ATT_SMEM 147456

__device__ __forceinline__ void attn_issue_kv(
    uint32_t smb, int tid, int st, size_t kb,
    const uint16_t* kh, const uint16_t* kl,
    const uint16_t* vh, const uint16_t* vl)
{
#pragma unroll
    for (int it = 0; it < 8; it++) {
        int idx = tid + it * 256;
        int a = idx >> 9;                  // 0 KH, 1 KL, 2 VH, 3 VL
        int c = idx & 511, row = c >> 3, cc = c & 7;
        const uint16_t* src =
            (a == 0 ? kh : a == 1 ? kl : a == 2 ? vh : vl) + kb + (size_t)row * EE + cc * 8;
        uint32_t dst = smb + (a < 2 ? AKB(st) : AVB(st)) + (a & 1) * 9216 + row * GPB + cc * 16;
        cpa16(dst, src);
    }
}

__global__ __launch_bounds__(256, 1)
void attn_bf(const uint16_t* __restrict__ qh, const uint16_t* __restrict__ ql,
             const uint16_t* __restrict__ kh, const uint16_t* __restrict__ kl,
             const uint16_t* __restrict__ vh, const uint16_t* __restrict__ vl,
             const int* __restrict__ mask,
             uint16_t* __restrict__ oh, uint16_t* __restrict__ ol)
{
    extern __shared__ char sm[];
    const uint32_t smb = smem_u32(sm);
    const int tid = threadIdx.x;
    const int q0 = blockIdx.x * 128;
    const int bh = blockIdx.y, b = bh >> 4, h = bh & 15, hoff = h * DHD;
    const int w = tid >> 5, lane = tid & 31;
    const int m0 = (w & 1) * 64, wn = w >> 1;
    const int n0 = wn * 16, d0 = wn * 16;
    const int r8 = lane & 7, quad = lane >> 3;
    const int arow = (quad & 1) * 8 + r8, acol = (quad >> 1) * 8;
    const int brow = (quad >> 1) * 8 + r8, bcol = (quad & 1) * 8;
    const int g = lane >> 2, t2 = (lane & 3) * 2;

    const size_t rowbase = (size_t)b * SS;

    // prologue: Q tile (group with stage0)
    const size_t qb = (rowbase + q0) * EE + hoff;
#pragma unroll
    for (int it = 0; it < 8; it++) {
        int idx = tid + it * 256;
        int a = idx >> 10, c = idx & 1023, row = c >> 3, cc = c & 7;
        const uint16_t* src = (a ? ql : qh) + qb + (size_t)row * EE + cc * 8;
        cpa16(smb + a * 18432 + row * GPB + cc * 16, src);
    }
    attn_issue_kv(smb, tid, 0, rowbase * EE + hoff, kh, kl, vh, vl);
    CPA_COMMIT();
    attn_issue_kv(smb, tid, 1, (rowbase + 64) * EE + hoff, kh, kl, vh, vl);
    CPA_COMMIT();

    float acc2[4][2][4];
#pragma unroll
    for (int i = 0; i < 4; i++)
#pragma unroll
        for (int j = 0; j < 2; j++)
#pragma unroll
            for (int k = 0; k < 4; k++) acc2[i][j][k] = 0.0f;

    for (int ht = 0; ht < 32; ht++) {
        CPA_WAIT1();
        __syncthreads();
        const int st = ht & 1;
        const uint32_t khs = smb + AKB(st), kls = khs + 9216;
        const uint32_t vhs = smb + AVB(st), vls = vhs + 9216;
        const int kg0 = ht * 64;

        // prefetch mask words for this half-tile (consumed after gemm1)
        int2 pma[4][2], pmb[4][2];
#pragma unroll
        for (int mf = 0; mf < 4; mf++)
#pragma unroll
            for (int nf = 0; nf < 2; nf++) {
                int rl = m0 + mf * 16 + g;
                int cl = n0 + nf * 8 + t2;
                const int* mp = mask + (rowbase + q0 + rl) * SS + kg0 + cl;
                pma[mf][nf] = *(const int2*)mp;
                pmb[mf][nf] = *(const int2*)(mp + (size_t)8 * SS);
            }

        // gemm1: S[128,64] = Qs[128,64] * Khalf[64,64]^T   (Q pre-scaled by 1/8)
        float acc1[4][2][4];
#pragma unroll
        for (int i = 0; i < 4; i++)
#pragma unroll
            for (int j = 0; j < 2; j++)
#pragma unroll
                for (int k = 0; k < 4; k++) acc1[i][j][k] = 0.0f;

#pragma unroll
        for (int kf = 0; kf < 4; kf++) {
            uint32_t bhf[2][2], blf[2][2], t[4];
            uint32_t boff = (uint32_t)((n0 + brow) * GP + kf * 16 + bcol) * 2;
            ldsm4(t, khs + boff);
            bhf[0][0] = t[0]; bhf[0][1] = t[1]; bhf[1][0] = t[2]; bhf[1][1] = t[3];
            ldsm4(t, kls + boff);
            blf[0][0] = t[0]; blf[0][1] = t[1]; blf[1][0] = t[2]; blf[1][1] = t[3];
#pragma unroll
            for (int mf = 0; mf < 4; mf++) {
                uint32_t ah[4], al[4];
                uint32_t aoff = (uint32_t)((m0 + mf * 16 + arow) * GP + kf * 16 + acol) * 2;
                ldsm4(ah, smb + AQH + aoff);
                ldsm4(al, smb + AQL + aoff);
#pragma unroll
                for (int nf = 0; nf < 2; nf++) {
                    mma_bf16(acc1[mf][nf], ah, bhf[nf]);
                    mma_bf16(acc1[mf][nf], ah, blf[nf]);
                    mma_bf16(acc1[mf][nf], al, bhf[nf]);
                }
            }
        }

        // mask + split-store S
#pragma unroll
        for (int mf = 0; mf < 4; mf++)
#pragma unroll
            for (int nf = 0; nf < 2; nf++) {
                int rl = m0 + mf * 16 + g;
                int cl = n0 + nf * 8 + t2;
                float v0 = pma[mf][nf].x ? acc1[mf][nf][0] : 1e-9f;
                float v1 = pma[mf][nf].y ? acc1[mf][nf][1] : 1e-9f;
                float v2 = pmb[mf][nf].x ? acc1[mf][nf][2] : 1e-9f;
                float v3 = pmb[mf][nf].y ? acc1[mf][nf][3] : 1e-9f;
                uint32_t hi, lo;
                split2(make_float2(v0, v1), hi, lo);
                *(uint32_t*)(sm + ASH + rl * GPB + cl * 2) = hi;
                *(uint32_t*)(sm + ASL + rl * GPB + cl * 2) = lo;
                split2(make_float2(v2, v3), hi, lo);
                *(uint32_t*)(sm + ASH + (rl + 8) * GPB + cl * 2) = hi;
                *(uint32_t*)(sm + ASL + (rl + 8) * GPB + cl * 2) = lo;
            }
        __syncthreads();

        // gemm2: O[128,64] += S[128,64] * Vhalf[64,64]
#pragma unroll
        for (int kf = 0; kf < 4; kf++) {
            uint32_t bhf[2][2], blf[2][2], t[4];
            uint32_t voff = (uint32_t)((kf * 16 + (quad & 1) * 8 + r8) * GP +
                                       d0 + (quad >> 1) * 8) * 2;
            ldsm4t(t, vhs + voff);
            bhf[0][0] = t[0]; bhf[0][1] = t[1]; bhf[1][0] = t[2]; bhf[1][1] = t[3];
            ldsm4t(t, vls + voff);
            blf[0][0] = t[0]; blf[0][1] = t[1]; blf[1][0] = t[2]; blf[1][1] = t[3];
#pragma unroll
            for (int mf = 0; mf < 4; mf++) {
                uint32_t sh[4], sl[4];
                uint32_t soff = (uint32_t)((m0 + mf * 16 + arow) * GP + kf * 16 + acol) * 2;
                ldsm4(sh, smb + ASH + soff);
                ldsm4(sl, smb + ASL + soff);
#pragma unroll
                for (int nf = 0; nf < 2; nf++) {
                    mma_bf16(acc2[mf][nf], sh, bhf[nf]);
                    mma_bf16(acc2[mf][nf], sh, blf[nf]);
                    mma_bf16(acc2[mf][nf], sl, bhf[nf]);
                }
            }
        }
        __syncthreads();
        if (ht + 2 < 32)
            attn_issue_kv(smb, tid, st, (rowbase + (ht + 2) * 64) * EE + hoff, kh, kl, vh, vl);
        CPA_COMMIT();
    }

    // epilogue: split O to hi/lo bf16
#pragma unroll
    for (int mf = 0; mf < 4; mf++)
#pragma unroll
        for (int nf = 0; nf < 2; nf++) {
            int row = q0 + m0 + mf * 16 + g;
            int col = hoff + d0 + nf * 8 + t2;
            uint32_t hi, lo;
            size_t off = (rowbase + row) * EE + col;
            split2(make_float2(acc2[mf][nf][0], acc2[mf][nf][1]), hi, lo);
            *(uint32_t*)(oh + off) = hi;
            *(uint32_t*)(ol + off) = lo;
            split2(make_float2(acc2[mf][nf][2], acc2[mf][nf][3]), hi, lo);
            off += (size_t)8 * EE;
            *(uint32_t*)(oh + off) = hi;
            *(uint32_t*)(ol + off) = lo;
        }
}

// ---------------------------------------------------------------------------
extern "C" void kernel_launch(void* const* d_in, const int* in_sizes, int n_in,
                              void* d_out, int out_size)
{
    const float* query = (const float*)d_in[0];
    const float* key   = (const float*)d_in[1];
    const float* value = (const float*)d_in[2];
    const int*   mask  = (const int*)  d_in[3];
    const float* Wq    = (const float*)d_in[4];
    const float* bq    = (const float*)d_in[5];
    const float* Wk    = (const float*)d_in[6];
    const float* bk    = (const float*)d_in[7];
    const float* Wv    = (const float*)d_in[8];
    const float* bv    = (const float*)d_in[9];
    const float* Wo    = (const float*)d_in[10];
    const float* bo    = (const float*)d_in[11];
    float* out = (float*)d_out;

    uint16_t *ih, *il, *wh, *wl, *ph, *pl, *oh, *ol;
    cudaGetSymbolAddress((void**)&ih, g_ih);
    cudaGetSymbolAddress((void**)&il, g_il);
    cudaGetSymbolAddress((void**)&wh, g_wh);
    cudaGetSymbolAddress((void**)&wl, g_wl);
    cudaGetSymbolAddress((void**)&ph, g_ph);
    cudaGetSymbolAddress((void**)&pl, g_pl);
    cudaGetSymbolAddress((void**)&oh, g_oh);
    cudaGetSymbolAddress((void**)&ol, g_ol);

    cudaFuncSetAttribute(gemm_bf, cudaFuncAttributeMaxDynamicSharedMemorySize, PRJ_SMEM);
    cudaFuncSetAttribute(attn_bf, cudaFuncAttributeMaxDynamicSharedMemorySize, ATT_SMEM);

    split_in<<<dim3(512, 3), 256>>>(query, key, value, ih, il);
    split_w<<<dim3(256, 4), 256>>>(Wq, Wk, Wv, Wo, wh, wl);

    dim3 pgrid(EE / 128, (BB * SS) / 128);   // (8, 32)
    // Q projection pre-scaled by 1/sqrt(DH) = 0.125 (exact power-of-2)
    gemm_bf<<<pgrid, 256, PRJ_SMEM>>>(ih,          il,          wh,          wl,          bq, 0.125f, 1, nullptr, ph,          pl);
    gemm_bf<<<pgrid, 256, PRJ_SMEM>>>(ih + ME,     il + ME,     wh + NE,     wl + NE,     bk, 1.0f,   1, nullptr, ph + ME,     pl + ME);
    gemm_bf<<<pgrid, 256, PRJ_SMEM>>>(ih + 2 * ME, il + 2 * ME, wh + 2 * NE, wl + 2 * NE, bv, 1.0f,   1, nullptr, ph + 2 * ME, pl + 2 * ME);

    dim3 agrid(SS / 128, BB * HH);   // (16, 32)
    attn_bf<<<agrid, 256, ATT_SMEM>>>(ph, pl, ph + ME, pl + ME, ph + 2 * ME, pl + 2 * ME,
                                      mask, oh, ol);

    gemm_bf<<<pgrid, 256, PRJ_SMEM>>>(oh, ol, wh + 3 * NE, wl + 3 * NE, bo, 1.0f, 0, out, nullptr, nullptr);
}

// round 9
// speedup vs baseline: 1.1699x; 1.1699x over previous
#include <cuda_runtime.h>
#include <cstdint>

#define BB 2
#define SS 2048
#define EE 1024
#define HH 16
#define DHD 64
#define ME (4096 * 1024)
#define NE (1024 * 1024)

// ---------------------------------------------------------------------------
// PTX helpers (base-sm_103 features only)
// ---------------------------------------------------------------------------
__device__ __forceinline__ uint32_t smem_u32(const void* p) {
    uint32_t a;
    asm("{ .reg .u64 t; cvta.to.shared.u64 t, %1; cvt.u32.u64 %0, t; }" : "=r"(a) : "l"(p));
    return a;
}
__device__ __forceinline__ void ldsm4(uint32_t r[4], uint32_t a) {
    asm volatile("ldmatrix.sync.aligned.m8n8.x4.shared.b16 {%0,%1,%2,%3}, [%4];"
                 : "=r"(r[0]), "=r"(r[1]), "=r"(r[2]), "=r"(r[3]) : "r"(a));
}
__device__ __forceinline__ void ldsm4t(uint32_t r[4], uint32_t a) {
    asm volatile("ldmatrix.sync.aligned.m8n8.x4.trans.shared.b16 {%0,%1,%2,%3}, [%4];"
                 : "=r"(r[0]), "=r"(r[1]), "=r"(r[2]), "=r"(r[3]) : "r"(a));
}
__device__ __forceinline__ void mma_bf16(float d[4], const uint32_t a[4], const uint32_t b[2]) {
    asm volatile("mma.sync.aligned.m16n8k16.row.col.f32.bf16.bf16.f32 "
                 "{%0,%1,%2,%3}, {%4,%5,%6,%7}, {%8,%9}, {%0,%1,%2,%3};"
                 : "+f"(d[0]), "+f"(d[1]), "+f"(d[2]), "+f"(d[3])
                 : "r"(a[0]), "r"(a[1]), "r"(a[2]), "r"(a[3]), "r"(b[0]), "r"(b[1]));
}
// split fp32 pair -> bf16x2 hi + bf16x2 lo (x = hi + lo, exact residual)
__device__ __forceinline__ void split2(float2 v, uint32_t& hi, uint32_t& lo) {
    asm("cvt.rn.bf16x2.f32 %0, %1, %2;" : "=r"(hi) : "f"(v.y), "f"(v.x));
    float h0 = __uint_as_float(hi << 16);
    float h1 = __uint_as_float(hi & 0xFFFF0000u);
    asm("cvt.rn.bf16x2.f32 %0, %1, %2;" : "=r"(lo) : "f"(v.y - h1), "f"(v.x - h0));
}
__device__ __forceinline__ void cpa16(uint32_t dst, const void* src) {
    asm volatile("cp.async.cg.shared.global [%0], [%1], 16;" :: "r"(dst), "l"(src));
}
#define CPA_COMMIT() asm volatile("cp.async.commit_group;" ::: "memory")
#define CPA_WAIT0()  asm volatile("cp.async.wait_group 0;" ::: "memory")
#define CPA_WAIT1()  asm volatile("cp.async.wait_group 1;" ::: "memory")

// ---------------------------------------------------------------------------
// Global bf16 hi/lo scratch (allocation-free)
// ---------------------------------------------------------------------------
__device__ uint16_t g_ih[3 * ME], g_il[3 * ME];   // split inputs q,k,v
__device__ uint16_t g_wh[4 * NE], g_wl[4 * NE];   // split weights q,k,v,o
__device__ uint16_t g_ph[3 * ME], g_pl[3 * ME];   // projected Q,K,V (hi/lo)
__device__ uint16_t g_oh[ME],     g_ol[ME];       // attention output (hi/lo)

// ---------------------------------------------------------------------------
// Prep: fp32 -> bf16 hi/lo
// ---------------------------------------------------------------------------
__global__ void split_in(const float* s0, const float* s1, const float* s2,
                         uint16_t* dh, uint16_t* dl)
{
    const float* src = (blockIdx.y == 0) ? s0 : (blockIdx.y == 1 ? s1 : s2);
    const float2* sp = (const float2*)src;
    uint32_t* hp = (uint32_t*)(dh + (size_t)blockIdx.y * ME);
    uint32_t* lp = (uint32_t*)(dl + (size_t)blockIdx.y * ME);
    const int n = ME / 2;
    for (int i = blockIdx.x * blockDim.x + threadIdx.x; i < n; i += gridDim.x * blockDim.x) {
        uint32_t h, l;
        split2(sp[i], h, l);
        hp[i] = h; lp[i] = l;
    }
}
__global__ void split_w(const float* s0, const float* s1, const float* s2, const float* s3,
                        uint16_t* dh, uint16_t* dl)
{
    const float* srcs[4] = {s0, s1, s2, s3};
    const float2* sp = (const float2*)srcs[blockIdx.y];
    uint32_t* hp = (uint32_t*)(dh + (size_t)blockIdx.y * NE);
    uint32_t* lp = (uint32_t*)(dl + (size_t)blockIdx.y * NE);
    const int n = NE / 2;
    for (int i = blockIdx.x * blockDim.x + threadIdx.x; i < n; i += gridDim.x * blockDim.x) {
        uint32_t h, l;
        split2(sp[i], h, l);
        hp[i] = h; lp[i] = l;
    }
}

// ---------------------------------------------------------------------------
// Projection GEMM body (R6 structure: BK=64, 16 serial stages, occ 2).
// C = (A*W^T + bias) * scale; mode 0: fp32 out, mode 1: bf16 hi/lo out.
// ---------------------------------------------------------------------------
#define GP 72
#define GPB 144
#define O_AHI 0
#define O_ALO 18432
#define O_BHI 36864
#define O_BLO 55296
#define PRJ_SMEM 73728

__device__ __forceinline__ void gemm_body(
    const uint16_t* __restrict__ Ah, const uint16_t* __restrict__ Al,
    const uint16_t* __restrict__ Wh, const uint16_t* __restrict__ Wl,
    const float* __restrict__ bias, float scale, int mode,
    float* __restrict__ Cf, uint16_t* __restrict__ Ch, uint16_t* __restrict__ Cl,
    char* sm, int bm, int bn)
{
    const uint32_t smb = smem_u32(sm);
    const int tid = threadIdx.x;
    const int w = tid >> 5, lane = tid & 31;
    const int m0 = (w & 1) * 64, n0 = (w >> 1) * 32;
    const int r8 = lane & 7, quad = lane >> 3;
    const int arow = (quad & 1) * 8 + r8, acol = (quad >> 1) * 8;
    const int brow = (quad >> 1) * 8 + r8, bcol = (quad & 1) * 8;

    float acc[4][4][4];
#pragma unroll
    for (int i = 0; i < 4; i++)
#pragma unroll
        for (int j = 0; j < 4; j++)
#pragma unroll
            for (int k = 0; k < 4; k++) acc[i][j][k] = 0.0f;

    for (int s = 0; s < 16; s++) {
        const int kk0 = s << 6;
        __syncthreads();
#pragma unroll
        for (int it = 0; it < 16; it++) {
            int idx = tid + it * 256;
            int a = idx >> 10, c = idx & 1023, row = c >> 3, cc = c & 7;
            const uint16_t* src;
            if (a == 0)      src = Ah + (size_t)(bm + row) * EE + kk0;
            else if (a == 1) src = Al + (size_t)(bm + row) * EE + kk0;
            else if (a == 2) src = Wh + (size_t)(bn + row) * EE + kk0;
            else             src = Wl + (size_t)(bn + row) * EE + kk0;
            cpa16(smb + a * 18432 + row * GPB + cc * 16, src + cc * 8);
        }
        CPA_COMMIT();
        CPA_WAIT0();
        __syncthreads();

#pragma unroll
        for (int kf = 0; kf < 4; kf++) {
            uint32_t bh[4][2], bl[4][2], t[4];
#pragma unroll
            for (int np = 0; np < 2; np++) {
                uint32_t boff = (uint32_t)((n0 + np * 16 + brow) * GP + kf * 16 + bcol) * 2;
                ldsm4(t, smb + O_BHI + boff);
                bh[np * 2][0] = t[0]; bh[np * 2][1] = t[1];
                bh[np * 2 + 1][0] = t[2]; bh[np * 2 + 1][1] = t[3];
                ldsm4(t, smb + O_BLO + boff);
                bl[np * 2][0] = t[0]; bl[np * 2][1] = t[1];
                bl[np * 2 + 1][0] = t[2]; bl[np * 2 + 1][1] = t[3];
            }
#pragma unroll
            for (int mf = 0; mf < 4; mf++) {
                uint32_t ah[4], al[4];
                uint32_t aoff = (uint32_t)((m0 + mf * 16 + arow) * GP + kf * 16 + acol) * 2;
                ldsm4(ah, smb + O_AHI + aoff);
                ldsm4(al, smb + O_ALO + aoff);
#pragma unroll
                for (int nf = 0; nf < 4; nf++) {
                    mma_bf16(acc[mf][nf], ah, bh[nf]);
                    mma_bf16(acc[mf][nf], ah, bl[nf]);
                    mma_bf16(acc[mf][nf], al, bh[nf]);
                }
            }
        }
    }

    const int g2 = lane >> 2, t2 = (lane & 3) * 2;
#pragma unroll
    for (int mf = 0; mf < 4; mf++)
#pragma unroll
        for (int nf = 0; nf < 4; nf++) {
            int row0 = bm + m0 + mf * 16 + g2;
            int col = bn + n0 + nf * 8 + t2;
            float b0 = bias[col], b1 = bias[col + 1];
            float v0 = (acc[mf][nf][0] + b0) * scale, v1 = (acc[mf][nf][1] + b1) * scale;
            float v2 = (acc[mf][nf][2] + b0) * scale, v3 = (acc[mf][nf][3] + b1) * scale;
            if (mode == 0) {
                *(float2*)(Cf + (size_t)row0 * EE + col) = make_float2(v0, v1);
                *(float2*)(Cf + (size_t)(row0 + 8) * EE + col) = make_float2(v2, v3);
            } else {
                uint32_t hi, lo;
                size_t off = (size_t)row0 * EE + col;
                split2(make_float2(v0, v1), hi, lo);
                *(uint32_t*)(Ch + off) = hi;
                *(uint32_t*)(Cl + off) = lo;
                split2(make_float2(v2, v3), hi, lo);
                off += (size_t)8 * EE;
                *(uint32_t*)(Ch + off) = hi;
                *(uint32_t*)(Cl + off) = lo;
            }
        }
}

// Fused Q/K/V projection: blockIdx.z selects problem. Q pre-scaled by 0.125.
__global__ __launch_bounds__(256, 2)
void gemm_qkv(const uint16_t* __restrict__ ih, const uint16_t* __restrict__ il,
              const uint16_t* __restrict__ wh, const uint16_t* __restrict__ wl,
              const float* __restrict__ bq, const float* __restrict__ bk,
              const float* __restrict__ bv,
              uint16_t* __restrict__ ph, uint16_t* __restrict__ pl)
{
    extern __shared__ char sm[];
    const int z = blockIdx.z;
    const float* bias = (z == 0) ? bq : (z == 1 ? bk : bv);
    gemm_body(ih + (size_t)z * ME, il + (size_t)z * ME,
              wh + (size_t)z * NE, wl + (size_t)z * NE,
              bias, (z == 0) ? 0.125f : 1.0f, 1,
              nullptr, ph + (size_t)z * ME, pl + (size_t)z * ME,
              sm, blockIdx.y * 128, blockIdx.x * 128);
}

// O projection: fp32 out
__global__ __launch_bounds__(256, 2)
void gemm_o(const uint16_t* __restrict__ oh, const uint16_t* __restrict__ ol,
            const uint16_t* __restrict__ wh, const uint16_t* __restrict__ wl,
            const float* __restrict__ bo, float* __restrict__ out)
{
    extern __shared__ char sm[];
    gemm_body(oh, ol, wh, wl, bo, 1.0f, 0, out, nullptr, nullptr,
              sm, blockIdx.y * 128, blockIdx.x * 128);
}

// ---------------------------------------------------------------------------
// Fused attention, register-resident S (NO softmax). Q pre-scaled by 1/8.
// Warp w owns q-rows [w*16, w*16+16) x full k range. gemm1 C-frags convert
// in-register to gemm2 A-frags (identical layouts). One barrier per half-tile.
// smem: QH/QL [128][72]; K,V double-buffered [64][72] hi+lo.
// ---------------------------------------------------------------------------
#define AQH 0
#define AQL 18432
#define AKB(st) (36864 + (st) * 18432)
#define AVB(st) (73728 + (st) * 18432)
#define ATT_SMEM 110592

__device__ __forceinline__ void attn_issue_kv(
    uint32_t smb, int tid, int st, size_t kb,
    const uint16_t* kh, const uint16_t* kl,
    const uint16_t* vh, const uint16_t* vl)
{
#pragma unroll
    for (int it = 0; it < 8; it++) {
        int idx = tid + it * 256;
        int a = idx >> 9;                  // 0 KH, 1 KL, 2 VH, 3 VL
        int c = idx & 511, row = c >> 3, cc = c & 7;
        const uint16_t* src =
            (a == 0 ? kh : a == 1 ? kl : a == 2 ? vh : vl) + kb + (size_t)row * EE + cc * 8;
        uint32_t dst = smb + (a < 2 ? AKB(st) : AVB(st)) + (a & 1) * 9216 + row * GPB + cc * 16;
        cpa16(dst, src);
    }
}

__global__ __launch_bounds__(256, 1)
void attn_bf(const uint16_t* __restrict__ qh, const uint16_t* __restrict__ ql,
             const uint16_t* __restrict__ kh, const uint16_t* __restrict__ kl,
             const uint16_t* __restrict__ vh, const uint16_t* __restrict__ vl,
             const int* __restrict__ mask,
             uint16_t* __restrict__ oh, uint16_t* __restrict__ ol)
{
    extern __shared__ char sm[];
    const uint32_t smb = smem_u32(sm);
    const int tid = threadIdx.x;
    const int q0 = blockIdx.x * 128;
    const int bh = blockIdx.y, b = bh >> 4, h = bh & 15, hoff = h * DHD;
    const int w = tid >> 5, lane = tid & 31;
    const int r8 = lane & 7, quad = lane >> 3;
    const int arow = (quad & 1) * 8 + r8, acol = (quad >> 1) * 8;
    const int brow = (quad >> 1) * 8 + r8, bcol = (quad & 1) * 8;
    const int g = lane >> 2, t2 = (lane & 3) * 2;

    const size_t rowbase = (size_t)b * SS;
    const size_t qb = (rowbase + q0) * EE + hoff;

    // prologue: Q tile + KV stage 0 (group0), KV stage 1 (group1)
#pragma unroll
    for (int it = 0; it < 8; it++) {
        int idx = tid + it * 256;
        int a = idx >> 10, c = idx & 1023, row = c >> 3, cc = c & 7;
        const uint16_t* src = (a ? ql : qh) + qb + (size_t)row * EE + cc * 8;
        cpa16(smb + a * 18432 + row * GPB + cc * 16, src);
    }
    attn_issue_kv(smb, tid, 0, rowbase * EE + hoff, kh, kl, vh, vl);
    CPA_COMMIT();
    attn_issue_kv(smb, tid, 1, (rowbase + 64) * EE + hoff, kh, kl, vh, vl);
    CPA_COMMIT();

    // wait group0 (Q + KV0), load Q fragments into registers permanently
    CPA_WAIT1();
    __syncthreads();
    uint32_t qfh[4][4], qfl[4][4];
#pragma unroll
    for (int kf = 0; kf < 4; kf++) {
        uint32_t aoff = (uint32_t)((w * 16 + arow) * GP + kf * 16 + acol) * 2;
        ldsm4(qfh[kf], smb + AQH + aoff);
        ldsm4(qfl[kf], smb + AQL + aoff);
    }

    float acc2[8][4];
#pragma unroll
    for (int j = 0; j < 8; j++)
#pragma unroll
        for (int k = 0; k < 4; k++) acc2[j][k] = 0.0f;

    const int mrow0 = (int)(rowbase + q0 + w * 16 + g);

    for (int ht = 0; ht < 32; ht++) {
        CPA_WAIT1();
        __syncthreads();
        const int st = ht & 1;
        const uint32_t khs = smb + AKB(st), kls = khs + 9216;
        const uint32_t vhs = smb + AVB(st), vls = vhs + 9216;
        const int kg0 = ht * 64;

        // prefetch mask (rows g, g+8 of this warp's 16-row strip)
        int2 mA[8], mB[8];
#pragma unroll
        for (int j = 0; j < 8; j++) {
            const int* mp = mask + (size_t)mrow0 * SS + kg0 + j * 8 + t2;
            mA[j] = *(const int2*)mp;
            mB[j] = *(const int2*)(mp + (size_t)8 * SS);
        }

        // gemm1: S[16,64] = Q[16,64] * Khalf[64,64]^T  (Q pre-scaled by 1/8)
        float acc1[8][4];
#pragma unroll
        for (int j = 0; j < 8; j++)
#pragma unroll
            for (int k = 0; k < 4; k++) acc1[j][k] = 0.0f;

#pragma unroll
        for (int kf = 0; kf < 4; kf++) {
            uint32_t bhf[8][2], blf[8][2], t[4];
#pragma unroll
            for (int np = 0; np < 4; np++) {
                uint32_t boff = (uint32_t)((np * 16 + brow) * GP + kf * 16 + bcol) * 2;
                ldsm4(t, khs + boff);
                bhf[np * 2][0] = t[0]; bhf[np * 2][1] = t[1];
                bhf[np * 2 + 1][0] = t[2]; bhf[np * 2 + 1][1] = t[3];
                ldsm4(t, kls + boff);
                blf[np * 2][0] = t[0]; blf[np * 2][1] = t[1];
                blf[np * 2 + 1][0] = t[2]; blf[np * 2 + 1][1] = t[3];
            }
#pragma unroll
            for (int nf = 0; nf < 8; nf++) {
                mma_bf16(acc1[nf], qfh[kf], bhf[nf]);
                mma_bf16(acc1[nf], qfh[kf], blf[nf]);
                mma_bf16(acc1[nf], qfl[kf], bhf[nf]);
            }
        }

        // mask in-register, split to S fragments (A-operand layout)
        uint32_t sfh[4][4], sfl[4][4];
#pragma unroll
        for (int j = 0; j < 8; j++) {
            float v0 = mA[j].x ? acc1[j][0] : 1e-9f;
            float v1 = mA[j].y ? acc1[j][1] : 1e-9f;
            float v2 = mB[j].x ? acc1[j][2] : 1e-9f;
            float v3 = mB[j].y ? acc1[j][3] : 1e-9f;
            int kf = j >> 1, hi2 = (j & 1) * 2;   // n-tile j -> A-frag kf, regs hi2/hi2+1
            split2(make_float2(v0, v1), sfh[kf][hi2], sfl[kf][hi2]);
            split2(make_float2(v2, v3), sfh[kf][hi2 + 1], sfl[kf][hi2 + 1]);
        }

        // gemm2: O[16,64] += S[16,64] * Vhalf[64,64]
#pragma unroll
        for (int kf = 0; kf < 4; kf++) {
            uint32_t bhf[8][2], blf[8][2], t[4];
#pragma unroll
            for (int dp = 0; dp < 4; dp++) {
                uint32_t voff = (uint32_t)((kf * 16 + (quad & 1) * 8 + r8) * GP +
                                           dp * 16 + (quad >> 1) * 8) * 2;
                ldsm4t(t, vhs + voff);
                bhf[dp * 2][0] = t[0]; bhf[dp * 2][1] = t[1];
                bhf[dp * 2 + 1][0] = t[2]; bhf[dp * 2 + 1][1] = t[3];
                ldsm4t(t, vls + voff);
                blf[dp * 2][0] = t[0]; blf[dp * 2][1] = t[1];
                blf[dp * 2 + 1][0] = t[2]; blf[dp * 2 + 1][1] = t[3];
            }
#pragma unroll
            for (int nf = 0; nf < 8; nf++) {
                mma_bf16(acc2[nf], sfh[kf], bhf[nf]);
                mma_bf16(acc2[nf], sfh[kf], blf[nf]);
                mma_bf16(acc2[nf], sfl[kf], bhf[nf]);
            }
        }
        __syncthreads();
        if (ht + 2 < 32)
            attn_issue_kv(smb, tid, st, (rowbase + (ht + 2) * 64) * EE + hoff, kh, kl, vh, vl);
        CPA_COMMIT();
    }

    // epilogue: split O to hi/lo bf16
#pragma unroll
    for (int j = 0; j < 8; j++) {
        int col = hoff + j * 8 + t2;
        size_t off = (size_t)mrow0 * EE + col;
        uint32_t hi, lo;
        split2(make_float2(acc2[j][0], acc2[j][1]), hi, lo);
        *(uint32_t*)(oh + off) = hi;
        *(uint32_t*)(ol + off) = lo;
        split2(make_float2(acc2[j][2], acc2[j][3]), hi, lo);
        off += (size_t)8 * EE;
        *(uint32_t*)(oh + off) = hi;
        *(uint32_t*)(ol + off) = lo;
    }
}

// ---------------------------------------------------------------------------
extern "C" void kernel_launch(void* const* d_in, const int* in_sizes, int n_in,
                              void* d_out, int out_size)
{
    const float* query = (const float*)d_in[0];
    const float* key   = (const float*)d_in[1];
    const float* value = (const float*)d_in[2];
    const int*   mask  = (const int*)  d_in[3];
    const float* Wq    = (const float*)d_in[4];
    const float* bq    = (const float*)d_in[5];
    const float* Wk    = (const float*)d_in[6];
    const float* bk    = (const float*)d_in[7];
    const float* Wv    = (const float*)d_in[8];
    const float* bv    = (const float*)d_in[9];
    const float* Wo    = (const float*)d_in[10];
    const float* bo    = (const float*)d_in[11];
    float* out = (float*)d_out;

    uint16_t *ih, *il, *wh, *wl, *ph, *pl, *oh, *ol;
    cudaGetSymbolAddress((void**)&ih, g_ih);
    cudaGetSymbolAddress((void**)&il, g_il);
    cudaGetSymbolAddress((void**)&wh, g_wh);
    cudaGetSymbolAddress((void**)&wl, g_wl);
    cudaGetSymbolAddress((void**)&ph, g_ph);
    cudaGetSymbolAddress((void**)&pl, g_pl);
    cudaGetSymbolAddress((void**)&oh, g_oh);
    cudaGetSymbolAddress((void**)&ol, g_ol);

    cudaFuncSetAttribute(gemm_qkv, cudaFuncAttributeMaxDynamicSharedMemorySize, PRJ_SMEM);
    cudaFuncSetAttribute(gemm_o,   cudaFuncAttributeMaxDynamicSharedMemorySize, PRJ_SMEM);
    cudaFuncSetAttribute(attn_bf,  cudaFuncAttributeMaxDynamicSharedMemorySize, ATT_SMEM);

    split_in<<<dim3(512, 3), 256>>>(query, key, value, ih, il);
    split_w<<<dim3(256, 4), 256>>>(Wq, Wk, Wv, Wo, wh, wl);

    dim3 qkvgrid(EE / 128, (BB * SS) / 128, 3);   // (8, 32, 3) = 768 CTAs
    gemm_qkv<<<qkvgrid, 256, PRJ_SMEM>>>(ih, il, wh, wl, bq, bk, bv, ph, pl);

    dim3 agrid(SS / 128, BB * HH);   // (16, 32)
    attn_bf<<<agrid, 256, ATT_SMEM>>>(ph, pl, ph + ME, pl + ME, ph + 2 * ME, pl + 2 * ME,
                                      mask, oh, ol);

    dim3 ogrid(EE / 128, (BB * SS) / 128);   // (8, 32)
    gemm_o<<<ogrid, 256, PRJ_SMEM>>>(oh, ol, wh + 3 * NE, wl + 3 * NE, bo, out);
}

// round 10
// speedup vs baseline: 1.1733x; 1.0030x over previous
#include <cuda_runtime.h>
#include <cstdint>

#define BB 2
#define SS 2048
#define EE 1024
#define HH 16
#define DHD 64
#define ME (4096 * 1024)
#define NE (1024 * 1024)

// ---------------------------------------------------------------------------
// PTX helpers (base-sm_103 features only)
// ---------------------------------------------------------------------------
__device__ __forceinline__ uint32_t smem_u32(const void* p) {
    uint32_t a;
    asm("{ .reg .u64 t; cvta.to.shared.u64 t, %1; cvt.u32.u64 %0, t; }" : "=r"(a) : "l"(p));
    return a;
}
__device__ __forceinline__ void ldsm4(uint32_t r[4], uint32_t a) {
    asm volatile("ldmatrix.sync.aligned.m8n8.x4.shared.b16 {%0,%1,%2,%3}, [%4];"
                 : "=r"(r[0]), "=r"(r[1]), "=r"(r[2]), "=r"(r[3]) : "r"(a));
}
__device__ __forceinline__ void ldsm4t(uint32_t r[4], uint32_t a) {
    asm volatile("ldmatrix.sync.aligned.m8n8.x4.trans.shared.b16 {%0,%1,%2,%3}, [%4];"
                 : "=r"(r[0]), "=r"(r[1]), "=r"(r[2]), "=r"(r[3]) : "r"(a));
}
__device__ __forceinline__ void mma_bf16(float d[4], const uint32_t a[4], const uint32_t b[2]) {
    asm volatile("mma.sync.aligned.m16n8k16.row.col.f32.bf16.bf16.f32 "
                 "{%0,%1,%2,%3}, {%4,%5,%6,%7}, {%8,%9}, {%0,%1,%2,%3};"
                 : "+f"(d[0]), "+f"(d[1]), "+f"(d[2]), "+f"(d[3])
                 : "r"(a[0]), "r"(a[1]), "r"(a[2]), "r"(a[3]), "r"(b[0]), "r"(b[1]));
}
// split fp32 pair -> bf16x2 hi + bf16x2 lo (x = hi + lo, exact residual)
__device__ __forceinline__ void split2(float2 v, uint32_t& hi, uint32_t& lo) {
    asm("cvt.rn.bf16x2.f32 %0, %1, %2;" : "=r"(hi) : "f"(v.y), "f"(v.x));
    float h0 = __uint_as_float(hi << 16);
    float h1 = __uint_as_float(hi & 0xFFFF0000u);
    asm("cvt.rn.bf16x2.f32 %0, %1, %2;" : "=r"(lo) : "f"(v.y - h1), "f"(v.x - h0));
}
__device__ __forceinline__ void cpa16(uint32_t dst, const void* src) {
    asm volatile("cp.async.cg.shared.global [%0], [%1], 16;" :: "r"(dst), "l"(src));
}
#define CPA_COMMIT() asm volatile("cp.async.commit_group;" ::: "memory")
#define CPA_WAIT0()  asm volatile("cp.async.wait_group 0;" ::: "memory")
#define CPA_WAIT1()  asm volatile("cp.async.wait_group 1;" ::: "memory")

// ---------------------------------------------------------------------------
// Global bf16 hi/lo scratch (allocation-free)
// ---------------------------------------------------------------------------
__device__ uint16_t g_ih[3 * ME], g_il[3 * ME];   // split inputs q,k,v
__device__ uint16_t g_wh[4 * NE], g_wl[4 * NE];   // split weights q,k,v,o
__device__ uint16_t g_ph[3 * ME], g_pl[3 * ME];   // projected Q,K,V (hi/lo)
__device__ uint16_t g_oh[ME],     g_ol[ME];       // attention output (hi/lo)

// ---------------------------------------------------------------------------
// Prep: fp32 -> bf16 hi/lo
// ---------------------------------------------------------------------------
__global__ void split_in(const float* s0, const float* s1, const float* s2,
                         uint16_t* dh, uint16_t* dl)
{
    const float* src = (blockIdx.y == 0) ? s0 : (blockIdx.y == 1 ? s1 : s2);
    const float2* sp = (const float2*)src;
    uint32_t* hp = (uint32_t*)(dh + (size_t)blockIdx.y * ME);
    uint32_t* lp = (uint32_t*)(dl + (size_t)blockIdx.y * ME);
    const int n = ME / 2;
    for (int i = blockIdx.x * blockDim.x + threadIdx.x; i < n; i += gridDim.x * blockDim.x) {
        uint32_t h, l;
        split2(sp[i], h, l);
        hp[i] = h; lp[i] = l;
    }
}
__global__ void split_w(const float* s0, const float* s1, const float* s2, const float* s3,
                        uint16_t* dh, uint16_t* dl)
{
    const float* srcs[4] = {s0, s1, s2, s3};
    const float2* sp = (const float2*)srcs[blockIdx.y];
    uint32_t* hp = (uint32_t*)(dh + (size_t)blockIdx.y * NE);
    uint32_t* lp = (uint32_t*)(dl + (size_t)blockIdx.y * NE);
    const int n = NE / 2;
    for (int i = blockIdx.x * blockDim.x + threadIdx.x; i < n; i += gridDim.x * blockDim.x) {
        uint32_t h, l;
        split2(sp[i], h, l);
        hp[i] = h; lp[i] = l;
    }
}

// ---------------------------------------------------------------------------
// Projection GEMM body (BK=64, 16 serial stages, occ 2) — unchanged from R9.
// ---------------------------------------------------------------------------
#define GP 72
#define GPB 144
#define O_AHI 0
#define O_ALO 18432
#define O_BHI 36864
#define O_BLO 55296
#define PRJ_SMEM 73728

__device__ __forceinline__ void gemm_body(
    const uint16_t* __restrict__ Ah, const uint16_t* __restrict__ Al,
    const uint16_t* __restrict__ Wh, const uint16_t* __restrict__ Wl,
    const float* __restrict__ bias, float scale, int mode,
    float* __restrict__ Cf, uint16_t* __restrict__ Ch, uint16_t* __restrict__ Cl,
    char* sm, int bm, int bn)
{
    const uint32_t smb = smem_u32(sm);
    const int tid = threadIdx.x;
    const int w = tid >> 5, lane = tid & 31;
    const int m0 = (w & 1) * 64, n0 = (w >> 1) * 32;
    const int r8 = lane & 7, quad = lane >> 3;
    const int arow = (quad & 1) * 8 + r8, acol = (quad >> 1) * 8;
    const int brow = (quad >> 1) * 8 + r8, bcol = (quad & 1) * 8;

    float acc[4][4][4];
#pragma unroll
    for (int i = 0; i < 4; i++)
#pragma unroll
        for (int j = 0; j < 4; j++)
#pragma unroll
            for (int k = 0; k < 4; k++) acc[i][j][k] = 0.0f;

    for (int s = 0; s < 16; s++) {
        const int kk0 = s << 6;
        __syncthreads();
#pragma unroll
        for (int it = 0; it < 16; it++) {
            int idx = tid + it * 256;
            int a = idx >> 10, c = idx & 1023, row = c >> 3, cc = c & 7;
            const uint16_t* src;
            if (a == 0)      src = Ah + (size_t)(bm + row) * EE + kk0;
            else if (a == 1) src = Al + (size_t)(bm + row) * EE + kk0;
            else if (a == 2) src = Wh + (size_t)(bn + row) * EE + kk0;
            else             src = Wl + (size_t)(bn + row) * EE + kk0;
            cpa16(smb + a * 18432 + row * GPB + cc * 16, src + cc * 8);
        }
        CPA_COMMIT();
        CPA_WAIT0();
        __syncthreads();

#pragma unroll
        for (int kf = 0; kf < 4; kf++) {
            uint32_t bh[4][2], bl[4][2], t[4];
#pragma unroll
            for (int np = 0; np < 2; np++) {
                uint32_t boff = (uint32_t)((n0 + np * 16 + brow) * GP + kf * 16 + bcol) * 2;
                ldsm4(t, smb + O_BHI + boff);
                bh[np * 2][0] = t[0]; bh[np * 2][1] = t[1];
                bh[np * 2 + 1][0] = t[2]; bh[np * 2 + 1][1] = t[3];
                ldsm4(t, smb + O_BLO + boff);
                bl[np * 2][0] = t[0]; bl[np * 2][1] = t[1];
                bl[np * 2 + 1][0] = t[2]; bl[np * 2 + 1][1] = t[3];
            }
#pragma unroll
            for (int mf = 0; mf < 4; mf++) {
                uint32_t ah[4], al[4];
                uint32_t aoff = (uint32_t)((m0 + mf * 16 + arow) * GP + kf * 16 + acol) * 2;
                ldsm4(ah, smb + O_AHI + aoff);
                ldsm4(al, smb + O_ALO + aoff);
#pragma unroll
                for (int nf = 0; nf < 4; nf++) {
                    mma_bf16(acc[mf][nf], ah, bh[nf]);
                    mma_bf16(acc[mf][nf], ah, bl[nf]);
                    mma_bf16(acc[mf][nf], al, bh[nf]);
                }
            }
        }
    }

    const int g2 = lane >> 2, t2 = (lane & 3) * 2;
#pragma unroll
    for (int mf = 0; mf < 4; mf++)
#pragma unroll
        for (int nf = 0; nf < 4; nf++) {
            int row0 = bm + m0 + mf * 16 + g2;
            int col = bn + n0 + nf * 8 + t2;
            float b0 = bias[col], b1 = bias[col + 1];
            float v0 = (acc[mf][nf][0] + b0) * scale, v1 = (acc[mf][nf][1] + b1) * scale;
            float v2 = (acc[mf][nf][2] + b0) * scale, v3 = (acc[mf][nf][3] + b1) * scale;
            if (mode == 0) {
                *(float2*)(Cf + (size_t)row0 * EE + col) = make_float2(v0, v1);
                *(float2*)(Cf + (size_t)(row0 + 8) * EE + col) = make_float2(v2, v3);
            } else {
                uint32_t hi, lo;
                size_t off = (size_t)row0 * EE + col;
                split2(make_float2(v0, v1), hi, lo);
                *(uint32_t*)(Ch + off) = hi;
                *(uint32_t*)(Cl + off) = lo;
                split2(make_float2(v2, v3), hi, lo);
                off += (size_t)8 * EE;
                *(uint32_t*)(Ch + off) = hi;
                *(uint32_t*)(Cl + off) = lo;
            }
        }
}

__global__ __launch_bounds__(256, 2)
void gemm_qkv(const uint16_t* __restrict__ ih, const uint16_t* __restrict__ il,
              const uint16_t* __restrict__ wh, const uint16_t* __restrict__ wl,
              const float* __restrict__ bq, const float* __restrict__ bk,
              const float* __restrict__ bv,
              uint16_t* __restrict__ ph, uint16_t* __restrict__ pl)
{
    extern __shared__ char sm[];
    const int z = blockIdx.z;
    const float* bias = (z == 0) ? bq : (z == 1 ? bk : bv);
    gemm_body(ih + (size_t)z * ME, il + (size_t)z * ME,
              wh + (size_t)z * NE, wl + (size_t)z * NE,
              bias, (z == 0) ? 0.125f : 1.0f, 1,
              nullptr, ph + (size_t)z * ME, pl + (size_t)z * ME,
              sm, blockIdx.y * 128, blockIdx.x * 128);
}

__global__ __launch_bounds__(256, 2)
void gemm_o(const uint16_t* __restrict__ oh, const uint16_t* __restrict__ ol,
            const uint16_t* __restrict__ wh, const uint16_t* __restrict__ wl,
            const float* __restrict__ bo, float* __restrict__ out)
{
    extern __shared__ char sm[];
    gemm_body(oh, ol, wh, wl, bo, 1.0f, 0, out, nullptr, nullptr,
              sm, blockIdx.y * 128, blockIdx.x * 128);
}

// ---------------------------------------------------------------------------
// Fused attention, register-resident S, 128 threads / q-tile 64, 2 CTAs/SM.
// Warp w owns q-rows [w*16, w*16+16). Mask prefetched before the stage wait.
// smem per CTA: QH/QL [64][72]; K,V double-buffered [64][72] hi+lo = 90 KB.
// ---------------------------------------------------------------------------
#define AQH 0
#define AQL 9216
#define AKB(st) (18432 + (st) * 36864)
#define ATT_SMEM 92160

__device__ __forceinline__ void attn_issue_kv(
    uint32_t smb, int tid, int st, size_t kb,
    const uint16_t* kh, const uint16_t* kl,
    const uint16_t* vh, const uint16_t* vl)
{
#pragma unroll
    for (int it = 0; it < 16; it++) {
        int idx = tid + it * 128;
        int a = idx >> 9;                  // 0 KH, 1 KL, 2 VH, 3 VL
        int c = idx & 511, row = c >> 3, cc = c & 7;
        const uint16_t* src =
            (a == 0 ? kh : a == 1 ? kl : a == 2 ? vh : vl) + kb + (size_t)row * EE + cc * 8;
        uint32_t dst = smb + AKB(st) + a * 9216 + row * GPB + cc * 16;
        cpa16(dst, src);
    }
}

__global__ __launch_bounds__(128)
void attn_bf(const uint16_t* __restrict__ qh, const uint16_t* __restrict__ ql,
             const uint16_t* __restrict__ kh, const uint16_t* __restrict__ kl,
             const uint16_t* __restrict__ vh, const uint16_t* __restrict__ vl,
             const int* __restrict__ mask,
             uint16_t* __restrict__ oh, uint16_t* __restrict__ ol)
{
    extern __shared__ char sm[];
    const uint32_t smb = smem_u32(sm);
    const int tid = threadIdx.x;
    const int q0 = blockIdx.x * 64;
    const int bh = blockIdx.y, b = bh >> 4, h = bh & 15, hoff = h * DHD;
    const int w = tid >> 5, lane = tid & 31;
    const int r8 = lane & 7, quad = lane >> 3;
    const int arow = (quad & 1) * 8 + r8, acol = (quad >> 1) * 8;
    const int brow = (quad >> 1) * 8 + r8, bcol = (quad & 1) * 8;
    const int g = lane >> 2, t2 = (lane & 3) * 2;

    const size_t rowbase = (size_t)b * SS;
    const size_t qb = (rowbase + q0) * EE + hoff;

    // prologue: Q tile (64 rows, hi+lo) + KV stage 0 (group0), KV stage 1 (group1)
#pragma unroll
    for (int it = 0; it < 8; it++) {
        int idx = tid + it * 128;          // 0..1023
        int a = idx >> 9, c = idx & 511, row = c >> 3, cc = c & 7;
        const uint16_t* src = (a ? ql : qh) + qb + (size_t)row * EE + cc * 8;
        cpa16(smb + a * 9216 + row * GPB + cc * 16, src);
    }
    attn_issue_kv(smb, tid, 0, rowbase * EE + hoff, kh, kl, vh, vl);
    CPA_COMMIT();
    attn_issue_kv(smb, tid, 1, (rowbase + 64) * EE + hoff, kh, kl, vh, vl);
    CPA_COMMIT();

    // wait group0 (Q + KV0), load Q fragments into registers permanently
    CPA_WAIT1();
    __syncthreads();
    uint32_t qfh[4][4], qfl[4][4];
#pragma unroll
    for (int kf = 0; kf < 4; kf++) {
        uint32_t aoff = (uint32_t)((w * 16 + arow) * GP + kf * 16 + acol) * 2;
        ldsm4(qfh[kf], smb + AQH + aoff);
        ldsm4(qfl[kf], smb + AQL + aoff);
    }

    float acc2[8][4];
#pragma unroll
    for (int j = 0; j < 8; j++)
#pragma unroll
        for (int k = 0; k < 4; k++) acc2[j][k] = 0.0f;

    const int mrow0 = (int)(rowbase + q0 + w * 16 + g);

    for (int ht = 0; ht < 32; ht++) {
        const int st = ht & 1;
        const int kg0 = ht * 64;

        // mask prefetch FIRST — independent of the pending K/V stage
        int2 mA[8], mB[8];
#pragma unroll
        for (int j = 0; j < 8; j++) {
            const int* mp = mask + (size_t)mrow0 * SS + kg0 + j * 8 + t2;
            mA[j] = *(const int2*)mp;
            mB[j] = *(const int2*)(mp + (size_t)8 * SS);
        }

        CPA_WAIT1();
        __syncthreads();
        const uint32_t khs = smb + AKB(st),      kls = khs + 9216;
        const uint32_t vhs = smb + AKB(st) + 18432, vls = vhs + 9216;

        // gemm1: S[16,64] = Q[16,64] * Khalf[64,64]^T  (Q pre-scaled by 1/8)
        float acc1[8][4];
#pragma unroll
        for (int j = 0; j < 8; j++)
#pragma unroll
            for (int k = 0; k < 4; k++) acc1[j][k] = 0.0f;

#pragma unroll
        for (int kf = 0; kf < 4; kf++) {
            uint32_t bhf[8][2], blf[8][2], t[4];
#pragma unroll
            for (int np = 0; np < 4; np++) {
                uint32_t boff = (uint32_t)((np * 16 + brow) * GP + kf * 16 + bcol) * 2;
                ldsm4(t, khs + boff);
                bhf[np * 2][0] = t[0]; bhf[np * 2][1] = t[1];
                bhf[np * 2 + 1][0] = t[2]; bhf[np * 2 + 1][1] = t[3];
                ldsm4(t, kls + boff);
                blf[np * 2][0] = t[0]; blf[np * 2][1] = t[1];
                blf[np * 2 + 1][0] = t[2]; blf[np * 2 + 1][1] = t[3];
            }
#pragma unroll
            for (int nf = 0; nf < 8; nf++) {
                mma_bf16(acc1[nf], qfh[kf], bhf[nf]);
                mma_bf16(acc1[nf], qfh[kf], blf[nf]);
                mma_bf16(acc1[nf], qfl[kf], bhf[nf]);
            }
        }

        // mask in-register, split to S fragments (A-operand layout)
        uint32_t sfh[4][4], sfl[4][4];
#pragma unroll
        for (int j = 0; j < 8; j++) {
            float v0 = mA[j].x ? acc1[j][0] : 1e-9f;
            float v1 = mA[j].y ? acc1[j][1] : 1e-9f;
            float v2 = mB[j].x ? acc1[j][2] : 1e-9f;
            float v3 = mB[j].y ? acc1[j][3] : 1e-9f;
            int kf = j >> 1, hi2 = (j & 1) * 2;
            split2(make_float2(v0, v1), sfh[kf][hi2], sfl[kf][hi2]);
            split2(make_float2(v2, v3), sfh[kf][hi2 + 1], sfl[kf][hi2 + 1]);
        }

        // gemm2: O[16,64] += S[16,64] * Vhalf[64,64]
#pragma unroll
        for (int kf = 0; kf < 4; kf++) {
            uint32_t bhf[8][2], blf[8][2], t[4];
#pragma unroll
            for (int dp = 0; dp < 4; dp++) {
                uint32_t voff = (uint32_t)((kf * 16 + (quad & 1) * 8 + r8) * GP +
                                           dp * 16 + (quad >> 1) * 8) * 2;
                ldsm4t(t, vhs + voff);
                bhf[dp * 2][0] = t[0]; bhf[dp * 2][1] = t[1];
                bhf[dp * 2 + 1][0] = t[2]; bhf[dp * 2 + 1][1] = t[3];
                ldsm4t(t, vls + voff);
                blf[dp * 2][0] = t[0]; blf[dp * 2][1] = t[1];
                blf[dp * 2 + 1][0] = t[2]; blf[dp * 2 + 1][1] = t[3];
            }
#pragma unroll
            for (int nf = 0; nf < 8; nf++) {
                mma_bf16(acc2[nf], sfh[kf], bhf[nf]);
                mma_bf16(acc2[nf], sfh[kf], blf[nf]);
                mma_bf16(acc2[nf], sfl[kf], bhf[nf]);
            }
        }
        __syncthreads();
        if (ht + 2 < 32)
            attn_issue_kv(smb, tid, st, (rowbase + (ht + 2) * 64) * EE + hoff, kh, kl, vh, vl);
        CPA_COMMIT();
    }

    // epilogue: split O to hi/lo bf16
#pragma unroll
    for (int j = 0; j < 8; j++) {
        int col = hoff + j * 8 + t2;
        size_t off = (size_t)mrow0 * EE + col;
        uint32_t hi, lo;
        split2(make_float2(acc2[j][0], acc2[j][1]), hi, lo);
        *(uint32_t*)(oh + off) = hi;
        *(uint32_t*)(ol + off) = lo;
        split2(make_float2(acc2[j][2], acc2[j][3]), hi, lo);
        off += (size_t)8 * EE;
        *(uint32_t*)(oh + off) = hi;
        *(uint32_t*)(ol + off) = lo;
    }
}

// ---------------------------------------------------------------------------
extern "C" void kernel_launch(void* const* d_in, const int* in_sizes, int n_in,
                              void* d_out, int out_size)
{
    const float* query = (const float*)d_in[0];
    const float* key   = (const float*)d_in[1];
    const float* value = (const float*)d_in[2];
    const int*   mask  = (const int*)  d_in[3];
    const float* Wq    = (const float*)d_in[4];
    const float* bq    = (const float*)d_in[5];
    const float* Wk    = (const float*)d_in[6];
    const float* bk    = (const float*)d_in[7];
    const float* Wv    = (const float*)d_in[8];
    const float* bv    = (const float*)d_in[9];
    const float* Wo    = (const float*)d_in[10];
    const float* bo    = (const float*)d_in[11];
    float* out = (float*)d_out;

    uint16_t *ih, *il, *wh, *wl, *ph, *pl, *oh, *ol;
    cudaGetSymbolAddress((void**)&ih, g_ih);
    cudaGetSymbolAddress((void**)&il, g_il);
    cudaGetSymbolAddress((void**)&wh, g_wh);
    cudaGetSymbolAddress((void**)&wl, g_wl);
    cudaGetSymbolAddress((void**)&ph, g_ph);
    cudaGetSymbolAddress((void**)&pl, g_pl);
    cudaGetSymbolAddress((void**)&oh, g_oh);
    cudaGetSymbolAddress((void**)&ol, g_ol);

    cudaFuncSetAttribute(gemm_qkv, cudaFuncAttributeMaxDynamicSharedMemorySize, PRJ_SMEM);
    cudaFuncSetAttribute(gemm_o,   cudaFuncAttributeMaxDynamicSharedMemorySize, PRJ_SMEM);
    cudaFuncSetAttribute(attn_bf,  cudaFuncAttributeMaxDynamicSharedMemorySize, ATT_SMEM);

    split_in<<<dim3(512, 3), 256>>>(query, key, value, ih, il);
    split_w<<<dim3(256, 4), 256>>>(Wq, Wk, Wv, Wo, wh, wl);

    dim3 qkvgrid(EE / 128, (BB * SS) / 128, 3);   // (8, 32, 3) = 768 CTAs
    gemm_qkv<<<qkvgrid, 256, PRJ_SMEM>>>(ih, il, wh, wl, bq, bk, bv, ph, pl);

    dim3 agrid(SS / 64, BB * HH);   // (32, 32) = 1024 CTAs, 2 per SM
    attn_bf<<<agrid, 128, ATT_SMEM>>>(ph, pl, ph + ME, pl + ME, ph + 2 * ME, pl + 2 * ME,
                                      mask, oh, ol);

    dim3 ogrid(EE / 128, (BB * SS) / 128);   // (8, 32)
    gemm_o<<<ogrid, 256, PRJ_SMEM>>>(oh, ol, wh + 3 * NE, wl + 3 * NE, bo, out);
}

// round 11
// speedup vs baseline: 1.2712x; 1.0834x over previous
#include <cuda_runtime.h>
#include <cstdint>

#define BB 2
#define SS 2048
#define EE 1024
#define HH 16
#define DHD 64
#define ME (4096 * 1024)
#define NE (1024 * 1024)

// ---------------------------------------------------------------------------
// PTX helpers (base-sm_103 features only)
// ---------------------------------------------------------------------------
__device__ __forceinline__ uint32_t smem_u32(const void* p) {
    uint32_t a;
    asm("{ .reg .u64 t; cvta.to.shared.u64 t, %1; cvt.u32.u64 %0, t; }" : "=r"(a) : "l"(p));
    return a;
}
__device__ __forceinline__ void ldsm4(uint32_t r[4], uint32_t a) {
    asm volatile("ldmatrix.sync.aligned.m8n8.x4.shared.b16 {%0,%1,%2,%3}, [%4];"
                 : "=r"(r[0]), "=r"(r[1]), "=r"(r[2]), "=r"(r[3]) : "r"(a));
}
__device__ __forceinline__ void ldsm4t(uint32_t r[4], uint32_t a) {
    asm volatile("ldmatrix.sync.aligned.m8n8.x4.trans.shared.b16 {%0,%1,%2,%3}, [%4];"
                 : "=r"(r[0]), "=r"(r[1]), "=r"(r[2]), "=r"(r[3]) : "r"(a));
}
__device__ __forceinline__ void mma_bf16(float d[4], const uint32_t a[4], const uint32_t b[2]) {
    asm volatile("mma.sync.aligned.m16n8k16.row.col.f32.bf16.bf16.f32 "
                 "{%0,%1,%2,%3}, {%4,%5,%6,%7}, {%8,%9}, {%0,%1,%2,%3};"
                 : "+f"(d[0]), "+f"(d[1]), "+f"(d[2]), "+f"(d[3])
                 : "r"(a[0]), "r"(a[1]), "r"(a[2]), "r"(a[3]), "r"(b[0]), "r"(b[1]));
}
// split fp32 pair -> bf16x2 hi + bf16x2 lo (x = hi + lo, exact residual)
__device__ __forceinline__ void split2(float2 v, uint32_t& hi, uint32_t& lo) {
    asm("cvt.rn.bf16x2.f32 %0, %1, %2;" : "=r"(hi) : "f"(v.y), "f"(v.x));
    float h0 = __uint_as_float(hi << 16);
    float h1 = __uint_as_float(hi & 0xFFFF0000u);
    asm("cvt.rn.bf16x2.f32 %0, %1, %2;" : "=r"(lo) : "f"(v.y - h1), "f"(v.x - h0));
}
__device__ __forceinline__ void cpa16(uint32_t dst, const void* src) {
    asm volatile("cp.async.cg.shared.global [%0], [%1], 16;" :: "r"(dst), "l"(src));
}
#define CPA_COMMIT() asm volatile("cp.async.commit_group;" ::: "memory")
#define CPA_WAIT0()  asm volatile("cp.async.wait_group 0;" ::: "memory")
#define CPA_WAIT1()  asm volatile("cp.async.wait_group 1;" ::: "memory")

// ---------------------------------------------------------------------------
// Global bf16 hi/lo scratch (allocation-free)
// ---------------------------------------------------------------------------
__device__ uint16_t g_ih[3 * ME], g_il[3 * ME];   // split inputs q,k,v
__device__ uint16_t g_wh[4 * NE], g_wl[4 * NE];   // split weights q,k,v,o
__device__ uint16_t g_ph[3 * ME], g_pl[3 * ME];   // projected Q,K,V (hi/lo)
__device__ uint16_t g_oh[ME],     g_ol[ME];       // attention output (hi/lo)

// ---------------------------------------------------------------------------
// Prep: fp32 -> bf16 hi/lo
// ---------------------------------------------------------------------------
__global__ void split_in(const float* s0, const float* s1, const float* s2,
                         uint16_t* dh, uint16_t* dl)
{
    const float* src = (blockIdx.y == 0) ? s0 : (blockIdx.y == 1 ? s1 : s2);
    const float2* sp = (const float2*)src;
    uint32_t* hp = (uint32_t*)(dh + (size_t)blockIdx.y * ME);
    uint32_t* lp = (uint32_t*)(dl + (size_t)blockIdx.y * ME);
    const int n = ME / 2;
    for (int i = blockIdx.x * blockDim.x + threadIdx.x; i < n; i += gridDim.x * blockDim.x) {
        uint32_t h, l;
        split2(sp[i], h, l);
        hp[i] = h; lp[i] = l;
    }
}
__global__ void split_w(const float* s0, const float* s1, const float* s2, const float* s3,
                        uint16_t* dh, uint16_t* dl)
{
    const float* srcs[4] = {s0, s1, s2, s3};
    const float2* sp = (const float2*)srcs[blockIdx.y];
    uint32_t* hp = (uint32_t*)(dh + (size_t)blockIdx.y * NE);
    uint32_t* lp = (uint32_t*)(dl + (size_t)blockIdx.y * NE);
    const int n = NE / 2;
    for (int i = blockIdx.x * blockDim.x + threadIdx.x; i < n; i += gridDim.x * blockDim.x) {
        uint32_t h, l;
        split2(sp[i], h, l);
        hp[i] = h; lp[i] = l;
    }
}

// ---------------------------------------------------------------------------
// Projection GEMM body (BK=64, 16 serial stages, occ 2) — unchanged.
// ---------------------------------------------------------------------------
#define GP 72
#define GPB 144
#define O_AHI 0
#define O_ALO 18432
#define O_BHI 36864
#define O_BLO 55296
#define PRJ_SMEM 73728

__device__ __forceinline__ void gemm_body(
    const uint16_t* __restrict__ Ah, const uint16_t* __restrict__ Al,
    const uint16_t* __restrict__ Wh, const uint16_t* __restrict__ Wl,
    const float* __restrict__ bias, float scale, int mode,
    float* __restrict__ Cf, uint16_t* __restrict__ Ch, uint16_t* __restrict__ Cl,
    char* sm, int bm, int bn)
{
    const uint32_t smb = smem_u32(sm);
    const int tid = threadIdx.x;
    const int w = tid >> 5, lane = tid & 31;
    const int m0 = (w & 1) * 64, n0 = (w >> 1) * 32;
    const int r8 = lane & 7, quad = lane >> 3;
    const int arow = (quad & 1) * 8 + r8, acol = (quad >> 1) * 8;
    const int brow = (quad >> 1) * 8 + r8, bcol = (quad & 1) * 8;

    float acc[4][4][4];
#pragma unroll
    for (int i = 0; i < 4; i++)
#pragma unroll
        for (int j = 0; j < 4; j++)
#pragma unroll
            for (int k = 0; k < 4; k++) acc[i][j][k] = 0.0f;

    for (int s = 0; s < 16; s++) {
        const int kk0 = s << 6;
        __syncthreads();
#pragma unroll
        for (int it = 0; it < 16; it++) {
            int idx = tid + it * 256;
            int a = idx >> 10, c = idx & 1023, row = c >> 3, cc = c & 7;
            const uint16_t* src;
            if (a == 0)      src = Ah + (size_t)(bm + row) * EE + kk0;
            else if (a == 1) src = Al + (size_t)(bm + row) * EE + kk0;
            else if (a == 2) src = Wh + (size_t)(bn + row) * EE + kk0;
            else             src = Wl + (size_t)(bn + row) * EE + kk0;
            cpa16(smb + a * 18432 + row * GPB + cc * 16, src + cc * 8);
        }
        CPA_COMMIT();
        CPA_WAIT0();
        __syncthreads();

#pragma unroll
        for (int kf = 0; kf < 4; kf++) {
            uint32_t bh[4][2], bl[4][2], t[4];
#pragma unroll
            for (int np = 0; np < 2; np++) {
                uint32_t boff = (uint32_t)((n0 + np * 16 + brow) * GP + kf * 16 + bcol) * 2;
                ldsm4(t, smb + O_BHI + boff);
                bh[np * 2][0] = t[0]; bh[np * 2][1] = t[1];
                bh[np * 2 + 1][0] = t[2]; bh[np * 2 + 1][1] = t[3];
                ldsm4(t, smb + O_BLO + boff);
                bl[np * 2][0] = t[0]; bl[np * 2][1] = t[1];
                bl[np * 2 + 1][0] = t[2]; bl[np * 2 + 1][1] = t[3];
            }
#pragma unroll
            for (int mf = 0; mf < 4; mf++) {
                uint32_t ah[4], al[4];
                uint32_t aoff = (uint32_t)((m0 + mf * 16 + arow) * GP + kf * 16 + acol) * 2;
                ldsm4(ah, smb + O_AHI + aoff);
                ldsm4(al, smb + O_ALO + aoff);
#pragma unroll
                for (int nf = 0; nf < 4; nf++) {
                    mma_bf16(acc[mf][nf], ah, bh[nf]);
                    mma_bf16(acc[mf][nf], ah, bl[nf]);
                    mma_bf16(acc[mf][nf], al, bh[nf]);
                }
            }
        }
    }

    const int g2 = lane >> 2, t2 = (lane & 3) * 2;
#pragma unroll
    for (int mf = 0; mf < 4; mf++)
#pragma unroll
        for (int nf = 0; nf < 4; nf++) {
            int row0 = bm + m0 + mf * 16 + g2;
            int col = bn + n0 + nf * 8 + t2;
            float b0 = bias[col], b1 = bias[col + 1];
            float v0 = (acc[mf][nf][0] + b0) * scale, v1 = (acc[mf][nf][1] + b1) * scale;
            float v2 = (acc[mf][nf][2] + b0) * scale, v3 = (acc[mf][nf][3] + b1) * scale;
            if (mode == 0) {
                *(float2*)(Cf + (size_t)row0 * EE + col) = make_float2(v0, v1);
                *(float2*)(Cf + (size_t)(row0 + 8) * EE + col) = make_float2(v2, v3);
            } else {
                uint32_t hi, lo;
                size_t off = (size_t)row0 * EE + col;
                split2(make_float2(v0, v1), hi, lo);
                *(uint32_t*)(Ch + off) = hi;
                *(uint32_t*)(Cl + off) = lo;
                split2(make_float2(v2, v3), hi, lo);
                off += (size_t)8 * EE;
                *(uint32_t*)(Ch + off) = hi;
                *(uint32_t*)(Cl + off) = lo;
            }
        }
}

__global__ __launch_bounds__(256, 2)
void gemm_qkv(const uint16_t* __restrict__ ih, const uint16_t* __restrict__ il,
              const uint16_t* __restrict__ wh, const uint16_t* __restrict__ wl,
              const float* __restrict__ bq, const float* __restrict__ bk,
              const float* __restrict__ bv,
              uint16_t* __restrict__ ph, uint16_t* __restrict__ pl)
{
    extern __shared__ char sm[];
    const int z = blockIdx.z;
    const float* bias = (z == 0) ? bq : (z == 1 ? bk : bv);
    gemm_body(ih + (size_t)z * ME, il + (size_t)z * ME,
              wh + (size_t)z * NE, wl + (size_t)z * NE,
              bias, (z == 0) ? 0.125f : 1.0f, 1,
              nullptr, ph + (size_t)z * ME, pl + (size_t)z * ME,
              sm, blockIdx.y * 128, blockIdx.x * 128);
}

__global__ __launch_bounds__(256, 2)
void gemm_o(const uint16_t* __restrict__ oh, const uint16_t* __restrict__ ol,
            const uint16_t* __restrict__ wh, const uint16_t* __restrict__ wl,
            const float* __restrict__ bo, float* __restrict__ out)
{
    extern __shared__ char sm[];
    gemm_body(oh, ol, wh, wl, bo, 1.0f, 0, out, nullptr, nullptr,
              sm, blockIdx.y * 128, blockIdx.x * 128);
}

// ---------------------------------------------------------------------------
// Fused attention: q-tile 64, K/V streamed in 32-row half-tiles (double-
// buffered), 128 threads, 4 CTAs/SM (54 KB smem, <=128 regs).
// Warp w owns q-rows [w*16, w*16+16). Register-resident S. Q pre-scaled 1/8.
// smem: QH/QL [64][72]; stages: K hi/lo + V hi/lo [32][72] each.
// ---------------------------------------------------------------------------
#define AQH 0
#define AQL 9216
#define STG_SZ 18432                       // 4 arrays x 32 rows x 144B
#define AKB(st) (18432 + (st) * STG_SZ)
#define ATT_SMEM 55296

__device__ __forceinline__ void attn_issue_kv(
    uint32_t smb, int tid, int st, size_t kb,
    const uint16_t* kh, const uint16_t* kl,
    const uint16_t* vh, const uint16_t* vl)
{
#pragma unroll
    for (int it = 0; it < 8; it++) {
        int idx = tid + it * 128;          // 0..1023
        int a = idx >> 8;                  // 0 KH, 1 KL, 2 VH, 3 VL (256 each)
        int c = idx & 255, row = c >> 3, cc = c & 7;
        const uint16_t* src =
            (a == 0 ? kh : a == 1 ? kl : a == 2 ? vh : vl) + kb + (size_t)row * EE + cc * 8;
        uint32_t dst = smb + AKB(st) + a * 4608 + row * GPB + cc * 16;
        cpa16(dst, src);
    }
}

__global__ __launch_bounds__(128, 4)
void attn_bf(const uint16_t* __restrict__ qh, const uint16_t* __restrict__ ql,
             const uint16_t* __restrict__ kh, const uint16_t* __restrict__ kl,
             const uint16_t* __restrict__ vh, const uint16_t* __restrict__ vl,
             const int* __restrict__ mask,
             uint16_t* __restrict__ oh, uint16_t* __restrict__ ol)
{
    extern __shared__ char sm[];
    const uint32_t smb = smem_u32(sm);
    const int tid = threadIdx.x;
    const int q0 = blockIdx.x * 64;
    const int bh = blockIdx.y, b = bh >> 4, h = bh & 15, hoff = h * DHD;
    const int w = tid >> 5, lane = tid & 31;
    const int r8 = lane & 7, quad = lane >> 3;
    const int arow = (quad & 1) * 8 + r8, acol = (quad >> 1) * 8;
    const int brow = (quad >> 1) * 8 + r8, bcol = (quad & 1) * 8;
    const int g = lane >> 2, t2 = (lane & 3) * 2;

    const size_t rowbase = (size_t)b * SS;
    const size_t qb = (rowbase + q0) * EE + hoff;

    // prologue: Q tile (64 rows hi+lo) + KV stage 0 (group0), KV stage 1 (group1)
#pragma unroll
    for (int it = 0; it < 8; it++) {
        int idx = tid + it * 128;          // 0..1023
        int a = idx >> 9, c = idx & 511, row = c >> 3, cc = c & 7;
        const uint16_t* src = (a ? ql : qh) + qb + (size_t)row * EE + cc * 8;
        cpa16(smb + a * 9216 + row * GPB + cc * 16, src);
    }
    attn_issue_kv(smb, tid, 0, rowbase * EE + hoff, kh, kl, vh, vl);
    CPA_COMMIT();
    attn_issue_kv(smb, tid, 1, (rowbase + 32) * EE + hoff, kh, kl, vh, vl);
    CPA_COMMIT();

    // wait group0 (Q + KV0), load Q fragments into registers permanently
    CPA_WAIT1();
    __syncthreads();
    uint32_t qfh[4][4], qfl[4][4];
#pragma unroll
    for (int kf = 0; kf < 4; kf++) {
        uint32_t aoff = (uint32_t)((w * 16 + arow) * GP + kf * 16 + acol) * 2;
        ldsm4(qfh[kf], smb + AQH + aoff);
        ldsm4(qfl[kf], smb + AQL + aoff);
    }

    float acc2[8][4];
#pragma unroll
    for (int j = 0; j < 8; j++)
#pragma unroll
        for (int k = 0; k < 4; k++) acc2[j][k] = 0.0f;

    const int mrow0 = (int)(rowbase + q0 + w * 16 + g);

    for (int ht = 0; ht < 64; ht++) {
        const int st = ht & 1;
        const int kg0 = ht * 32;

        // mask prefetch FIRST — independent of the pending K/V stage
        int2 mA[4], mB[4];
#pragma unroll
        for (int j = 0; j < 4; j++) {
            const int* mp = mask + (size_t)mrow0 * SS + kg0 + j * 8 + t2;
            mA[j] = *(const int2*)mp;
            mB[j] = *(const int2*)(mp + (size_t)8 * SS);
        }

        CPA_WAIT1();
        __syncthreads();
        const uint32_t khs = smb + AKB(st),        kls = khs + 4608;
        const uint32_t vhs = smb + AKB(st) + 9216, vls = vhs + 4608;

        // gemm1: S[16,32] = Q[16,64] * Khalf[32,64]^T  (Q pre-scaled by 1/8)
        float acc1[4][4];
#pragma unroll
        for (int j = 0; j < 4; j++)
#pragma unroll
            for (int k = 0; k < 4; k++) acc1[j][k] = 0.0f;

#pragma unroll
        for (int kf = 0; kf < 4; kf++) {
            uint32_t bhf[4][2], blf[4][2], t[4];
#pragma unroll
            for (int np = 0; np < 2; np++) {
                uint32_t boff = (uint32_t)((np * 16 + brow) * GP + kf * 16 + bcol) * 2;
                ldsm4(t, khs + boff);
                bhf[np * 2][0] = t[0]; bhf[np * 2][1] = t[1];
                bhf[np * 2 + 1][0] = t[2]; bhf[np * 2 + 1][1] = t[3];
                ldsm4(t, kls + boff);
                blf[np * 2][0] = t[0]; blf[np * 2][1] = t[1];
                blf[np * 2 + 1][0] = t[2]; blf[np * 2 + 1][1] = t[3];
            }
#pragma unroll
            for (int nf = 0; nf < 4; nf++) {
                mma_bf16(acc1[nf], qfh[kf], bhf[nf]);
                mma_bf16(acc1[nf], qfh[kf], blf[nf]);
                mma_bf16(acc1[nf], qfl[kf], bhf[nf]);
            }
        }

        // mask in-register, split to S fragments (A-operand layout, k-dim 32)
        uint32_t sfh[2][4], sfl[2][4];
#pragma unroll
        for (int j = 0; j < 4; j++) {
            float v0 = mA[j].x ? acc1[j][0] : 1e-9f;
            float v1 = mA[j].y ? acc1[j][1] : 1e-9f;
            float v2 = mB[j].x ? acc1[j][2] : 1e-9f;
            float v3 = mB[j].y ? acc1[j][3] : 1e-9f;
            int kf = j >> 1, hi2 = (j & 1) * 2;
            split2(make_float2(v0, v1), sfh[kf][hi2], sfl[kf][hi2]);
            split2(make_float2(v2, v3), sfh[kf][hi2 + 1], sfl[kf][hi2 + 1]);
        }

        // gemm2: O[16,64] += S[16,32] * Vhalf[32,64]
#pragma unroll
        for (int kf = 0; kf < 2; kf++) {
            uint32_t bhf[8][2], blf[8][2], t[4];
#pragma unroll
            for (int dp = 0; dp < 4; dp++) {
                uint32_t voff = (uint32_t)((kf * 16 + (quad & 1) * 8 + r8) * GP +
                                           dp * 16 + (quad >> 1) * 8) * 2;
                ldsm4t(t, vhs + voff);
                bhf[dp * 2][0] = t[0]; bhf[dp * 2][1] = t[1];
                bhf[dp * 2 + 1][0] = t[2]; bhf[dp * 2 + 1][1] = t[3];
                ldsm4t(t, vls + voff);
                blf[dp * 2][0] = t[0]; blf[dp * 2][1] = t[1];
                blf[dp * 2 + 1][0] = t[2]; blf[dp * 2 + 1][1] = t[3];
            }
#pragma unroll
            for (int nf = 0; nf < 8; nf++) {
                mma_bf16(acc2[nf], sfh[kf], bhf[nf]);
                mma_bf16(acc2[nf], sfh[kf], blf[nf]);
                mma_bf16(acc2[nf], sfl[kf], bhf[nf]);
            }
        }
        __syncthreads();
        if (ht + 2 < 64)
            attn_issue_kv(smb, tid, st, (rowbase + (ht + 2) * 32) * EE + hoff, kh, kl, vh, vl);
        CPA_COMMIT();
    }

    // epilogue: split O to hi/lo bf16
#pragma unroll
    for (int j = 0; j < 8; j++) {
        int col = hoff + j * 8 + t2;
        size_t off = (size_t)mrow0 * EE + col;
        uint32_t hi, lo;
        split2(make_float2(acc2[j][0], acc2[j][1]), hi, lo);
        *(uint32_t*)(oh + off) = hi;
        *(uint32_t*)(ol + off) = lo;
        split2(make_float2(acc2[j][2], acc2[j][3]), hi, lo);
        off += (size_t)8 * EE;
        *(uint32_t*)(oh + off) = hi;
        *(uint32_t*)(ol + off) = lo;
    }
}

// ---------------------------------------------------------------------------
extern "C" void kernel_launch(void* const* d_in, const int* in_sizes, int n_in,
                              void* d_out, int out_size)
{
    const float* query = (const float*)d_in[0];
    const float* key   = (const float*)d_in[1];
    const float* value = (const float*)d_in[2];
    const int*   mask  = (const int*)  d_in[3];
    const float* Wq    = (const float*)d_in[4];
    const float* bq    = (const float*)d_in[5];
    const float* Wk    = (const float*)d_in[6];
    const float* bk    = (const float*)d_in[7];
    const float* Wv    = (const float*)d_in[8];
    const float* bv    = (const float*)d_in[9];
    const float* Wo    = (const float*)d_in[10];
    const float* bo    = (const float*)d_in[11];
    float* out = (float*)d_out;

    uint16_t *ih, *il, *wh, *wl, *ph, *pl, *oh, *ol;
    cudaGetSymbolAddress((void**)&ih, g_ih);
    cudaGetSymbolAddress((void**)&il, g_il);
    cudaGetSymbolAddress((void**)&wh, g_wh);
    cudaGetSymbolAddress((void**)&wl, g_wl);
    cudaGetSymbolAddress((void**)&ph, g_ph);
    cudaGetSymbolAddress((void**)&pl, g_pl);
    cudaGetSymbolAddress((void**)&oh, g_oh);
    cudaGetSymbolAddress((void**)&ol, g_ol);

    cudaFuncSetAttribute(gemm_qkv, cudaFuncAttributeMaxDynamicSharedMemorySize, PRJ_SMEM);
    cudaFuncSetAttribute(gemm_o,   cudaFuncAttributeMaxDynamicSharedMemorySize, PRJ_SMEM);
    cudaFuncSetAttribute(attn_bf,  cudaFuncAttributeMaxDynamicSharedMemorySize, ATT_SMEM);

    split_in<<<dim3(512, 3), 256>>>(query, key, value, ih, il);
    split_w<<<dim3(256, 4), 256>>>(Wq, Wk, Wv, Wo, wh, wl);

    dim3 qkvgrid(EE / 128, (BB * SS) / 128, 3);   // (8, 32, 3) = 768 CTAs
    gemm_qkv<<<qkvgrid, 256, PRJ_SMEM>>>(ih, il, wh, wl, bq, bk, bv, ph, pl);

    dim3 agrid(SS / 64, BB * HH);   // (32, 32) = 1024 CTAs, 4 per SM
    attn_bf<<<agrid, 128, ATT_SMEM>>>(ph, pl, ph + ME, pl + ME, ph + 2 * ME, pl + 2 * ME,
                                      mask, oh, ol);

    dim3 ogrid(EE / 128, (BB * SS) / 128);   // (8, 32)
    gemm_o<<<ogrid, 256, PRJ_SMEM>>>(oh, ol, wh + 3 * NE, wl + 3 * NE, bo, out);
}

// round 12
// speedup vs baseline: 1.2869x; 1.0124x over previous
#include <cuda_runtime.h>
#include <cstdint>

#define BB 2
#define SS 2048
#define EE 1024
#define HH 16
#define DHD 64
#define ME (4096 * 1024)
#define NE (1024 * 1024)

// ---------------------------------------------------------------------------
// PTX helpers (base-sm_103 features only)
// ---------------------------------------------------------------------------
__device__ __forceinline__ uint32_t smem_u32(const void* p) {
    uint32_t a;
    asm("{ .reg .u64 t; cvta.to.shared.u64 t, %1; cvt.u32.u64 %0, t; }" : "=r"(a) : "l"(p));
    return a;
}
__device__ __forceinline__ void ldsm4(uint32_t r[4], uint32_t a) {
    asm volatile("ldmatrix.sync.aligned.m8n8.x4.shared.b16 {%0,%1,%2,%3}, [%4];"
                 : "=r"(r[0]), "=r"(r[1]), "=r"(r[2]), "=r"(r[3]) : "r"(a));
}
__device__ __forceinline__ void ldsm4t(uint32_t r[4], uint32_t a) {
    asm volatile("ldmatrix.sync.aligned.m8n8.x4.trans.shared.b16 {%0,%1,%2,%3}, [%4];"
                 : "=r"(r[0]), "=r"(r[1]), "=r"(r[2]), "=r"(r[3]) : "r"(a));
}
__device__ __forceinline__ void mma_bf16(float d[4], const uint32_t a[4], const uint32_t b[2]) {
    asm volatile("mma.sync.aligned.m16n8k16.row.col.f32.bf16.bf16.f32 "
                 "{%0,%1,%2,%3}, {%4,%5,%6,%7}, {%8,%9}, {%0,%1,%2,%3};"
                 : "+f"(d[0]), "+f"(d[1]), "+f"(d[2]), "+f"(d[3])
                 : "r"(a[0]), "r"(a[1]), "r"(a[2]), "r"(a[3]), "r"(b[0]), "r"(b[1]));
}
// split fp32 pair -> bf16x2 hi + bf16x2 lo (x = hi + lo, exact residual)
__device__ __forceinline__ void split2(float2 v, uint32_t& hi, uint32_t& lo) {
    asm("cvt.rn.bf16x2.f32 %0, %1, %2;" : "=r"(hi) : "f"(v.y), "f"(v.x));
    float h0 = __uint_as_float(hi << 16);
    float h1 = __uint_as_float(hi & 0xFFFF0000u);
    asm("cvt.rn.bf16x2.f32 %0, %1, %2;" : "=r"(lo) : "f"(v.y - h1), "f"(v.x - h0));
}
__device__ __forceinline__ void cpa16(uint32_t dst, const void* src) {
    asm volatile("cp.async.cg.shared.global [%0], [%1], 16;" :: "r"(dst), "l"(src));
}
#define CPA_COMMIT() asm volatile("cp.async.commit_group;" ::: "memory")
#define CPA_WAIT0()  asm volatile("cp.async.wait_group 0;" ::: "memory")
#define CPA_WAIT1()  asm volatile("cp.async.wait_group 1;" ::: "memory")

// ---------------------------------------------------------------------------
// Global bf16 hi/lo scratch (allocation-free)
// ---------------------------------------------------------------------------
__device__ uint16_t g_ih[3 * ME], g_il[3 * ME];   // split inputs q,k,v
__device__ uint16_t g_wh[4 * NE], g_wl[4 * NE];   // split weights q,k,v,o
__device__ uint16_t g_ph[3 * ME], g_pl[3 * ME];   // projected Q,K,V (hi/lo)
__device__ uint16_t g_oh[ME],     g_ol[ME];       // attention output (hi/lo)

// ---------------------------------------------------------------------------
// Prep: fp32 -> bf16 hi/lo (inputs + weights in ONE launch; z selects tensor)
// ---------------------------------------------------------------------------
__global__ void split_all(const float* q, const float* k, const float* v,
                          const float* wq, const float* wk, const float* wv,
                          const float* wo,
                          uint16_t* ih, uint16_t* il,
                          uint16_t* wh, uint16_t* wl)
{
    const int z = blockIdx.y;
    const float2* sp;
    uint32_t *hp, *lp;
    int n;
    if (z < 3) {
        sp = (const float2*)(z == 0 ? q : z == 1 ? k : v);
        hp = (uint32_t*)(ih + (size_t)z * ME);
        lp = (uint32_t*)(il + (size_t)z * ME);
        n = ME / 2;
    } else {
        const int y = z - 3;
        sp = (const float2*)(y == 0 ? wq : y == 1 ? wk : y == 2 ? wv : wo);
        hp = (uint32_t*)(wh + (size_t)y * NE);
        lp = (uint32_t*)(wl + (size_t)y * NE);
        n = NE / 2;
    }
    for (int i = blockIdx.x * blockDim.x + threadIdx.x; i < n; i += gridDim.x * blockDim.x) {
        uint32_t h, l;
        split2(sp[i], h, l);
        hp[i] = h; lp[i] = l;
    }
}

// ---------------------------------------------------------------------------
// Projection GEMM body (BK=64, 16 serial stages, occ 2) — unchanged.
// ---------------------------------------------------------------------------
#define GP 72
#define GPB 144
#define O_AHI 0
#define O_ALO 18432
#define O_BHI 36864
#define O_BLO 55296
#define PRJ_SMEM 73728

__device__ __forceinline__ void gemm_body(
    const uint16_t* __restrict__ Ah, const uint16_t* __restrict__ Al,
    const uint16_t* __restrict__ Wh, const uint16_t* __restrict__ Wl,
    const float* __restrict__ bias, float scale, int mode,
    float* __restrict__ Cf, uint16_t* __restrict__ Ch, uint16_t* __restrict__ Cl,
    char* sm, int bm, int bn)
{
    const uint32_t smb = smem_u32(sm);
    const int tid = threadIdx.x;
    const int w = tid >> 5, lane = tid & 31;
    const int m0 = (w & 1) * 64, n0 = (w >> 1) * 32;
    const int r8 = lane & 7, quad = lane >> 3;
    const int arow = (quad & 1) * 8 + r8, acol = (quad >> 1) * 8;
    const int brow = (quad >> 1) * 8 + r8, bcol = (quad & 1) * 8;

    float acc[4][4][4];
#pragma unroll
    for (int i = 0; i < 4; i++)
#pragma unroll
        for (int j = 0; j < 4; j++)
#pragma unroll
            for (int k = 0; k < 4; k++) acc[i][j][k] = 0.0f;

    for (int s = 0; s < 16; s++) {
        const int kk0 = s << 6;
        __syncthreads();
#pragma unroll
        for (int it = 0; it < 16; it++) {
            int idx = tid + it * 256;
            int a = idx >> 10, c = idx & 1023, row = c >> 3, cc = c & 7;
            const uint16_t* src;
            if (a == 0)      src = Ah + (size_t)(bm + row) * EE + kk0;
            else if (a == 1) src = Al + (size_t)(bm + row) * EE + kk0;
            else if (a == 2) src = Wh + (size_t)(bn + row) * EE + kk0;
            else             src = Wl + (size_t)(bn + row) * EE + kk0;
            cpa16(smb + a * 18432 + row * GPB + cc * 16, src + cc * 8);
        }
        CPA_COMMIT();
        CPA_WAIT0();
        __syncthreads();

#pragma unroll
        for (int kf = 0; kf < 4; kf++) {
            uint32_t bh[4][2], bl[4][2], t[4];
#pragma unroll
            for (int np = 0; np < 2; np++) {
                uint32_t boff = (uint32_t)((n0 + np * 16 + brow) * GP + kf * 16 + bcol) * 2;
                ldsm4(t, smb + O_BHI + boff);
                bh[np * 2][0] = t[0]; bh[np * 2][1] = t[1];
                bh[np * 2 + 1][0] = t[2]; bh[np * 2 + 1][1] = t[3];
                ldsm4(t, smb + O_BLO + boff);
                bl[np * 2][0] = t[0]; bl[np * 2][1] = t[1];
                bl[np * 2 + 1][0] = t[2]; bl[np * 2 + 1][1] = t[3];
            }
#pragma unroll
            for (int mf = 0; mf < 4; mf++) {
                uint32_t ah[4], al[4];
                uint32_t aoff = (uint32_t)((m0 + mf * 16 + arow) * GP + kf * 16 + acol) * 2;
                ldsm4(ah, smb + O_AHI + aoff);
                ldsm4(al, smb + O_ALO + aoff);
#pragma unroll
                for (int nf = 0; nf < 4; nf++) {
                    mma_bf16(acc[mf][nf], ah, bh[nf]);
                    mma_bf16(acc[mf][nf], ah, bl[nf]);
                    mma_bf16(acc[mf][nf], al, bh[nf]);
                }
            }
        }
    }

    const int g2 = lane >> 2, t2 = (lane & 3) * 2;
#pragma unroll
    for (int mf = 0; mf < 4; mf++)
#pragma unroll
        for (int nf = 0; nf < 4; nf++) {
            int row0 = bm + m0 + mf * 16 + g2;
            int col = bn + n0 + nf * 8 + t2;
            float b0 = bias[col], b1 = bias[col + 1];
            float v0 = (acc[mf][nf][0] + b0) * scale, v1 = (acc[mf][nf][1] + b1) * scale;
            float v2 = (acc[mf][nf][2] + b0) * scale, v3 = (acc[mf][nf][3] + b1) * scale;
            if (mode == 0) {
                *(float2*)(Cf + (size_t)row0 * EE + col) = make_float2(v0, v1);
                *(float2*)(Cf + (size_t)(row0 + 8) * EE + col) = make_float2(v2, v3);
            } else {
                uint32_t hi, lo;
                size_t off = (size_t)row0 * EE + col;
                split2(make_float2(v0, v1), hi, lo);
                *(uint32_t*)(Ch + off) = hi;
                *(uint32_t*)(Cl + off) = lo;
                split2(make_float2(v2, v3), hi, lo);
                off += (size_t)8 * EE;
                *(uint32_t*)(Ch + off) = hi;
                *(uint32_t*)(Cl + off) = lo;
            }
        }
}

__global__ __launch_bounds__(256, 2)
void gemm_qkv(const uint16_t* __restrict__ ih, const uint16_t* __restrict__ il,
              const uint16_t* __restrict__ wh, const uint16_t* __restrict__ wl,
              const float* __restrict__ bq, const float* __restrict__ bk,
              const float* __restrict__ bv,
              uint16_t* __restrict__ ph, uint16_t* __restrict__ pl)
{
    extern __shared__ char sm[];
    const int z = blockIdx.z;
    const float* bias = (z == 0) ? bq : (z == 1 ? bk : bv);
    gemm_body(ih + (size_t)z * ME, il + (size_t)z * ME,
              wh + (size_t)z * NE, wl + (size_t)z * NE,
              bias, (z == 0) ? 0.125f : 1.0f, 1,
              nullptr, ph + (size_t)z * ME, pl + (size_t)z * ME,
              sm, blockIdx.y * 128, blockIdx.x * 128);
}

__global__ __launch_bounds__(256, 2)
void gemm_o(const uint16_t* __restrict__ oh, const uint16_t* __restrict__ ol,
            const uint16_t* __restrict__ wh, const uint16_t* __restrict__ wl,
            const float* __restrict__ bo, float* __restrict__ out)
{
    extern __shared__ char sm[];
    gemm_body(oh, ol, wh, wl, bo, 1.0f, 0, out, nullptr, nullptr,
              sm, blockIdx.y * 128, blockIdx.x * 128);
}

// ---------------------------------------------------------------------------
// Fused attention: q-tile 64, k-tile 32, 128 threads, 4 CTAs/SM.
// THREE rotating 18432B K/V buffers; buffer 0 doubles as the Q staging area
// (Q lives in registers after the prologue). ONE barrier per iteration:
// prefetch for stage s+2 targets the buffer consumed at s-1, so it is issued
// right after the iteration's single sync. Q pre-scaled by 1/8.
// Buffer map: KV(s) lives at base ((s+1)%3)*18432.
// ---------------------------------------------------------------------------
#define ATT_SMEM 55296

__device__ __forceinline__ void attn_issue_kv(
    uint32_t smb, int tid, uint32_t bufbase, size_t kb,
    const uint16_t* kh, const uint16_t* kl,
    const uint16_t* vh, const uint16_t* vl)
{
#pragma unroll
    for (int it = 0; it < 8; it++) {
        int idx = tid + it * 128;          // 0..1023
        int a = idx >> 8;                  // 0 KH, 1 KL, 2 VH, 3 VL (256 each)
        int c = idx & 255, row = c >> 3, cc = c & 7;
        const uint16_t* src =
            (a == 0 ? kh : a == 1 ? kl : a == 2 ? vh : vl) + kb + (size_t)row * EE + cc * 8;
        uint32_t dst = smb + bufbase + a * 4608 + row * GPB + cc * 16;
        cpa16(dst, src);
    }
}

__global__ __launch_bounds__(128, 4)
void attn_bf(const uint16_t* __restrict__ qh, const uint16_t* __restrict__ ql,
             const uint16_t* __restrict__ kh, const uint16_t* __restrict__ kl,
             const uint16_t* __restrict__ vh, const uint16_t* __restrict__ vl,
             const int* __restrict__ mask,
             uint16_t* __restrict__ oh, uint16_t* __restrict__ ol)
{
    extern __shared__ char sm[];
    const uint32_t smb = smem_u32(sm);
    const int tid = threadIdx.x;
    const int q0 = blockIdx.x * 64;
    const int bh = blockIdx.y, b = bh >> 4, h = bh & 15, hoff = h * DHD;
    const int w = tid >> 5, lane = tid & 31;
    const int r8 = lane & 7, quad = lane >> 3;
    const int arow = (quad & 1) * 8 + r8, acol = (quad >> 1) * 8;
    const int brow = (quad >> 1) * 8 + r8, bcol = (quad & 1) * 8;
    const int g = lane >> 2, t2 = (lane & 3) * 2;

    const size_t rowbase = (size_t)b * SS;
    const size_t qb = (rowbase + q0) * EE + hoff;

    // prologue: Q tile -> buffer 0 (hi @0, lo @9216); KV(0) -> buf1; KV(1) -> buf2
#pragma unroll
    for (int it = 0; it < 8; it++) {
        int idx = tid + it * 128;          // 0..1023
        int a = idx >> 9, c = idx & 511, row = c >> 3, cc = c & 7;
        const uint16_t* src = (a ? ql : qh) + qb + (size_t)row * EE + cc * 8;
        cpa16(smb + a * 9216 + row * GPB + cc * 16, src);
    }
    attn_issue_kv(smb, tid, 18432, rowbase * EE + hoff, kh, kl, vh, vl);
    CPA_COMMIT();                         // group0: Q + KV(0)
    attn_issue_kv(smb, tid, 36864, (rowbase + 32) * EE + hoff, kh, kl, vh, vl);
    CPA_COMMIT();                         // group1: KV(1)

    // wait group0 (Q + KV0), load Q fragments into registers permanently
    CPA_WAIT1();
    __syncthreads();
    uint32_t qfh[4][4], qfl[4][4];
#pragma unroll
    for (int kf = 0; kf < 4; kf++) {
        uint32_t aoff = (uint32_t)((w * 16 + arow) * GP + kf * 16 + acol) * 2;
        ldsm4(qfh[kf], smb + aoff);
        ldsm4(qfl[kf], smb + 9216 + aoff);
    }

    float acc2[8][4];
#pragma unroll
    for (int j = 0; j < 8; j++)
#pragma unroll
        for (int k = 0; k < 4; k++) acc2[j][k] = 0.0f;

    const int mrow0 = (int)(rowbase + q0 + w * 16 + g);

    int jb = 1;                            // buffer index of current stage: (s+1)%3
    for (int ht = 0; ht < 64; ht++) {
        const int kg0 = ht * 32;
        const uint32_t cb = (uint32_t)jb * 18432u;
        int pj = jb + 2; if (pj >= 3) pj -= 3;
        const uint32_t pb = (uint32_t)pj * 18432u;

        // mask prefetch FIRST — independent of the pending K/V stage
        int2 mA[4], mB[4];
#pragma unroll
        for (int j = 0; j < 4; j++) {
            const int* mp = mask + (size_t)mrow0 * SS + kg0 + j * 8 + t2;
            mA[j] = *(const int2*)mp;
            mB[j] = *(const int2*)(mp + (size_t)8 * SS);
        }

        CPA_WAIT1();                       // KV(ht) complete (KV(ht+1) may be in flight)
        __syncthreads();                   // (a) data visible (b) compute(ht-1) done -> pb free

        // issue prefetch for stage ht+2 into the freed buffer, then compute
        if (ht + 2 < 64)
            attn_issue_kv(smb, tid, pb, (rowbase + (ht + 2) * 32) * EE + hoff, kh, kl, vh, vl);
        CPA_COMMIT();

        const uint32_t khs = smb + cb,        kls = khs + 4608;
        const uint32_t vhs = smb + cb + 9216, vls = vhs + 4608;

        // gemm1: S[16,32] = Q[16,64] * Khalf[32,64]^T  (Q pre-scaled by 1/8)
        float acc1[4][4];
#pragma unroll
        for (int j = 0; j < 4; j++)
#pragma unroll
            for (int k = 0; k < 4; k++) acc1[j][k] = 0.0f;

#pragma unroll
        for (int kf = 0; kf < 4; kf++) {
            uint32_t bhf[4][2], blf[4][2], t[4];
#pragma unroll
            for (int np = 0; np < 2; np++) {
                uint32_t boff = (uint32_t)((np * 16 + brow) * GP + kf * 16 + bcol) * 2;
                ldsm4(t, khs + boff);
                bhf[np * 2][0] = t[0]; bhf[np * 2][1] = t[1];
                bhf[np * 2 + 1][0] = t[2]; bhf[np * 2 + 1][1] = t[3];
                ldsm4(t, kls + boff);
                blf[np * 2][0] = t[0]; blf[np * 2][1] = t[1];
                blf[np * 2 + 1][0] = t[2]; blf[np * 2 + 1][1] = t[3];
            }
#pragma unroll
            for (int nf = 0; nf < 4; nf++) {
                mma_bf16(acc1[nf], qfh[kf], bhf[nf]);
                mma_bf16(acc1[nf], qfh[kf], blf[nf]);
                mma_bf16(acc1[nf], qfl[kf], bhf[nf]);
            }
        }

        // mask in-register, split to S fragments (A-operand layout, k-dim 32)
        uint32_t sfh[2][4], sfl[2][4];
#pragma unroll
        for (int j = 0; j < 4; j++) {
            float v0 = mA[j].x ? acc1[j][0] : 1e-9f;
            float v1 = mA[j].y ? acc1[j][1] : 1e-9f;
            float v2 = mB[j].x ? acc1[j][2] : 1e-9f;
            float v3 = mB[j].y ? acc1[j][3] : 1e-9f;
            int kf = j >> 1, hi2 = (j & 1) * 2;
            split2(make_float2(v0, v1), sfh[kf][hi2], sfl[kf][hi2]);
            split2(make_float2(v2, v3), sfh[kf][hi2 + 1], sfl[kf][hi2 + 1]);
        }

        // gemm2: O[16,64] += S[16,32] * Vhalf[32,64]
#pragma unroll
        for (int kf = 0; kf < 2; kf++) {
            uint32_t bhf[8][2], blf[8][2], t[4];
#pragma unroll
            for (int dp = 0; dp < 4; dp++) {
                uint32_t voff = (uint32_t)((kf * 16 + (quad & 1) * 8 + r8) * GP +
                                           dp * 16 + (quad >> 1) * 8) * 2;
                ldsm4t(t, vhs + voff);
                bhf[dp * 2][0] = t[0]; bhf[dp * 2][1] = t[1];
                bhf[dp * 2 + 1][0] = t[2]; bhf[dp * 2 + 1][1] = t[3];
                ldsm4t(t, vls + voff);
                blf[dp * 2][0] = t[0]; blf[dp * 2][1] = t[1];
                blf[dp * 2 + 1][0] = t[2]; blf[dp * 2 + 1][1] = t[3];
            }
#pragma unroll
            for (int nf = 0; nf < 8; nf++) {
                mma_bf16(acc2[nf], sfh[kf], bhf[nf]);
                mma_bf16(acc2[nf], sfh[kf], blf[nf]);
                mma_bf16(acc2[nf], sfl[kf], bhf[nf]);
            }
        }
        // NO trailing barrier — next iteration's single sync guards the rotation.
        jb++; if (jb == 3) jb = 0;
    }

    // epilogue: split O to hi/lo bf16
#pragma unroll
    for (int j = 0; j < 8; j++) {
        int col = hoff + j * 8 + t2;
        size_t off = (size_t)mrow0 * EE + col;
        uint32_t hi, lo;
        split2(make_float2(acc2[j][0], acc2[j][1]), hi, lo);
        *(uint32_t*)(oh + off) = hi;
        *(uint32_t*)(ol + off) = lo;
        split2(make_float2(acc2[j][2], acc2[j][3]), hi, lo);
        off += (size_t)8 * EE;
        *(uint32_t*)(oh + off) = hi;
        *(uint32_t*)(ol + off) = lo;
    }
}

// ---------------------------------------------------------------------------
extern "C" void kernel_launch(void* const* d_in, const int* in_sizes, int n_in,
                              void* d_out, int out_size)
{
    const float* query = (const float*)d_in[0];
    const float* key   = (const float*)d_in[1];
    const float* value = (const float*)d_in[2];
    const int*   mask  = (const int*)  d_in[3];
    const float* Wq    = (const float*)d_in[4];
    const float* bq    = (const float*)d_in[5];
    const float* Wk    = (const float*)d_in[6];
    const float* bk    = (const float*)d_in[7];
    const float* Wv    = (const float*)d_in[8];
    const float* bv    = (const float*)d_in[9];
    const float* Wo    = (const float*)d_in[10];
    const float* bo    = (const float*)d_in[11];
    float* out = (float*)d_out;

    uint16_t *ih, *il, *wh, *wl, *ph, *pl, *oh, *ol;
    cudaGetSymbolAddress((void**)&ih, g_ih);
    cudaGetSymbolAddress((void**)&il, g_il);
    cudaGetSymbolAddress((void**)&wh, g_wh);
    cudaGetSymbolAddress((void**)&wl, g_wl);
    cudaGetSymbolAddress((void**)&ph, g_ph);
    cudaGetSymbolAddress((void**)&pl, g_pl);
    cudaGetSymbolAddress((void**)&oh, g_oh);
    cudaGetSymbolAddress((void**)&ol, g_ol);

    cudaFuncSetAttribute(gemm_qkv, cudaFuncAttributeMaxDynamicSharedMemorySize, PRJ_SMEM);
    cudaFuncSetAttribute(gemm_o,   cudaFuncAttributeMaxDynamicSharedMemorySize, PRJ_SMEM);
    cudaFuncSetAttribute(attn_bf,  cudaFuncAttributeMaxDynamicSharedMemorySize, ATT_SMEM);

    split_all<<<dim3(384, 7), 256>>>(query, key, value, Wq, Wk, Wv, Wo, ih, il, wh, wl);

    dim3 qkvgrid(EE / 128, (BB * SS) / 128, 3);   // (8, 32, 3) = 768 CTAs
    gemm_qkv<<<qkvgrid, 256, PRJ_SMEM>>>(ih, il, wh, wl, bq, bk, bv, ph, pl);

    dim3 agrid(SS / 64, BB * HH);   // (32, 32) = 1024 CTAs, 4 per SM
    attn_bf<<<agrid, 128, ATT_SMEM>>>(ph, pl, ph + ME, pl + ME, ph + 2 * ME, pl + 2 * ME,
                                      mask, oh, ol);

    dim3 ogrid(EE / 128, (BB * SS) / 128);   // (8, 32)
    gemm_o<<<ogrid, 256, PRJ_SMEM>>>(oh, ol, wh + 3 * NE, wl + 3 * NE, bo, out);
}